// round 14
// baseline (speedup 1.0000x reference)
#include <cuda_runtime.h>
#include <cuda_bf16.h>

// Problem constants (fixed shapes)
#define N_MAX 50000
#define M_MAX 800000
#define D 96          // K*FAC
#define KCAP 8
#define FAC 12

#define CAP 18                        // cached neighbors per node in smem (bf16)
#define WSLAB (CAP * 768)             // per-warp slab: CAP entries x 768B
#define ROUTE_SMEM (4 * WSLAB)        // 55296 B per 128-thread block -> 4 blocks/SM
#define ROUTE_GRID 592                // 148 SMs x 4 resident blocks: exactly one wave

typedef unsigned long long u64;

// Static scratch (no allocations allowed)
__device__ __nv_bfloat16 g_zh_a[N_MAX * D];  // bf16 z double-buffer A (gather source)
__device__ __nv_bfloat16 g_zh_b[N_MAX * D];  // bf16 z double-buffer B
__device__ float  g_z32_a[N_MAX * D];  // fp32 z double-buffer A (self-term)
__device__ float  g_z32_b[N_MAX * D];  // fp32 z double-buffer B
__device__ float  g_wt[D * 256];       // W transposed to [out=96][in=256]
__device__ int    g_deg[N_MAX];
__device__ int    g_rowptr[N_MAX + 1];
__device__ int    g_cursor[N_MAX];
__device__ int    g_colsrc[M_MAX];
__device__ int    g_bsum[64];
__device__ int    g_boff[64];
__device__ int    g_dhist[64];
__device__ int    g_dcur[64];
__device__ int    g_perm[N_MAX];
__device__ int    g_work[4];           // per-layer work-stealing counters
__device__ int    g_bar[4];            // per-layer global barrier counters

// ---------------- packed f32x2 helpers (FFMA2 via PTX) ---------------------
__device__ __forceinline__ u64 pk2(float lo, float hi) {
    u64 r; asm("mov.b64 %0,{%1,%2};" : "=l"(r) : "f"(lo), "f"(hi)); return r;
}
__device__ __forceinline__ float2 upk2(u64 v) {
    float2 f; asm("mov.b64 {%0,%1},%2;" : "=f"(f.x), "=f"(f.y) : "l"(v)); return f;
}
__device__ __forceinline__ u64 fma2_(u64 a, u64 b, u64 c) {
    u64 d; asm("fma.rn.f32x2 %0,%1,%2,%3;" : "=l"(d) : "l"(a), "l"(b), "l"(c)); return d;
}
__device__ __forceinline__ u64 mul2_(u64 a, u64 b) {
    u64 d; asm("mul.rn.f32x2 %0,%1,%2;" : "=l"(d) : "l"(a), "l"(b)); return d;
}
__device__ __forceinline__ u64 add2_(u64 a, u64 b) {
    u64 d; asm("add.rn.f32x2 %0,%1,%2;" : "=l"(d) : "l"(a), "l"(b)); return d;
}

// bf16 pair unpack: pure ALU bit-ops (no F2F pipe)
__device__ __forceinline__ float bflo(unsigned u) { return __uint_as_float(u << 16); }
__device__ __forceinline__ float bfhi(unsigned u) { return __uint_as_float(u & 0xffff0000u); }

// 8-lane group sum (3-shuffle butterfly; fp32 redux unsupported on sm_103)
__device__ __forceinline__ float gsum8(float v, unsigned mask) {
    v += __shfl_xor_sync(mask, v, 1);
    v += __shfl_xor_sync(mask, v, 2);
    v += __shfl_xor_sync(mask, v, 4);
    return v;
}

// ---------------------------------------------------------------------------
// zero + W transpose fused; also resets work/barrier counters each replay.
__global__ void zero_wt_kernel(const float* __restrict__ W, int n) {
    int i = blockIdx.x * blockDim.x + threadIdx.x;
    if (i < n) g_deg[i] = 0;
    if (i < 64) g_dhist[i] = 0;
    if (i < 4) { g_work[i] = 0; g_bar[i] = 0; }
    if (i < D * 256) {
        int o = i >> 8, c = i & 255;
        int k = o / FAC, oo = o % FAC;
        g_wt[i] = W[k * (256 * FAC) + c * FAC + oo];
    }
}

// ---------------------------------------------------------------------------
// Init layer fused with prep: Z = relu(X.Wt + b) staged in smem, then
// z = l2norm(Z) written to z32_a (fp32) + zh_a (bf16). f32x2 FMA mainloop.
__global__ void __launch_bounds__(96) init_gemm(const float* __restrict__ X,
                                                const float* __restrict__ bv, int n) {
    __shared__ float xs[32][256];
    __shared__ float os[32][96];
    int t = threadIdx.x;
    int nb = blockIdx.x * 32;
    for (int j = t; j < 32 * 256; j += 96) {
        int q = j >> 8;
        xs[q][j & 255] = (nb + q < n) ? X[nb * 256 + j] : 0.f;
    }
    __syncthreads();

    u64 acc[32];
#pragma unroll
    for (int q = 0; q < 32; q++) acc[q] = 0ull;

    const float4* wrow = (const float4*)(g_wt + t * 256);
#pragma unroll 2
    for (int i4 = 0; i4 < 64; i4++) {
        float4 w = wrow[i4];
        u64 w01 = pk2(w.x, w.y);
        u64 w23 = pk2(w.z, w.w);
#pragma unroll
        for (int q = 0; q < 32; q++) {
            float4 xv = *(const float4*)&xs[q][i4 * 4];
            acc[q] = fma2_(w01, pk2(xv.x, xv.y), acc[q]);
            acc[q] = fma2_(w23, pk2(xv.z, xv.w), acc[q]);
        }
    }
    float bb = bv[t];
#pragma unroll
    for (int q = 0; q < 32; q++) {
        float2 h = upk2(acc[q]);
        os[q][t] = fmaxf(h.x + h.y + bb, 0.f);   // relu(Z)
    }
    __syncthreads();

    // prep: per (node, capsule) l2norm -> z32_a + zh_a (bf16)
    for (int idx = t; idx < 32 * KCAP; idx += 96) {
        int q = idx >> 3, cp = idx & 7;
        if (nb + q >= n) continue;
        const float* r = &os[q][cp * FAC];
        float v[12];
        float s = 0.f;
#pragma unroll
        for (int i = 0; i < 12; i++) { v[i] = r[i]; s += v[i] * v[i]; }
        float rn = rsqrtf(s + 1e-12f);
#pragma unroll
        for (int i = 0; i < 12; i++) v[i] *= rn;
        int gi = ((nb + q) * KCAP + cp) * FAC;
        float4* zp = (float4*)(g_z32_a + gi);
        zp[0] = make_float4(v[0], v[1], v[2], v[3]);
        zp[1] = make_float4(v[4], v[5], v[6], v[7]);
        zp[2] = make_float4(v[8], v[9], v[10], v[11]);
        uint2* zh = (uint2*)(g_zh_a + gi);
        __nv_bfloat162 b0 = __floats2bfloat162_rn(v[0], v[1]);
        __nv_bfloat162 b1 = __floats2bfloat162_rn(v[2], v[3]);
        __nv_bfloat162 b2 = __floats2bfloat162_rn(v[4], v[5]);
        __nv_bfloat162 b3 = __floats2bfloat162_rn(v[6], v[7]);
        __nv_bfloat162 b4 = __floats2bfloat162_rn(v[8], v[9]);
        __nv_bfloat162 b5 = __floats2bfloat162_rn(v[10], v[11]);
        zh[0] = make_uint2(*(unsigned*)&b0, *(unsigned*)&b1);
        zh[1] = make_uint2(*(unsigned*)&b2, *(unsigned*)&b3);
        zh[2] = make_uint2(*(unsigned*)&b4, *(unsigned*)&b5);
    }
}

// ---------------------------------------------------------------------------
// CSR build: hist -> 3-phase hierarchical scan (with perm stages fused)
__global__ void hist_kernel(const int* __restrict__ edges, int m) {
    int e = blockIdx.x * blockDim.x + threadIdx.x;
    if (e < m) atomicAdd(&g_deg[edges[m + e]], 1);
}

__global__ void scan1_kernel(int n) {
    __shared__ int wsum[32];
    __shared__ int h[64];
    int t = threadIdx.x, lane = t & 31, wid = t >> 5;
    if (t < 64) h[t] = 0;
    int idx = blockIdx.x * 1024 + t;
    int v = (idx < n) ? g_deg[idx] : 0;
    int x = v;
#pragma unroll
    for (int off = 1; off < 32; off <<= 1) {
        int y = __shfl_up_sync(0xffffffffu, x, off);
        if (lane >= off) x += y;
    }
    if (lane == 31) wsum[wid] = x;
    __syncthreads();
    if (wid == 0) {
        int w = wsum[lane];
#pragma unroll
        for (int off = 1; off < 32; off <<= 1) {
            int y = __shfl_up_sync(0xffffffffu, w, off);
            if (lane >= off) w += y;
        }
        wsum[lane] = w;
    }
    if (idx < n) atomicAdd(&h[min(v, 63)], 1);
    __syncthreads();
    int pre = (wid > 0) ? wsum[wid - 1] : 0;
    if (idx < n) g_rowptr[idx] = pre + x - v;   // block-local exclusive
    if (t == 1023) g_bsum[blockIdx.x] = pre + x;
    if (t < 64 && h[t]) atomicAdd(&g_dhist[t], h[t]);
}

__global__ void scan2_kernel(int nblocks, int n) {
    int t = threadIdx.x;  // 64 threads
    int v = (t < nblocks) ? g_bsum[t] : 0;
    int x = v;
    int lane = t & 31, wid = t >> 5;
    __shared__ int ws[2];
#pragma unroll
    for (int off = 1; off < 32; off <<= 1) {
        int y = __shfl_up_sync(0xffffffffu, x, off);
        if (lane >= off) x += y;
    }
    if (lane == 31) ws[wid] = x;
    __syncthreads();
    int add = (wid == 1) ? ws[0] : 0;
    g_boff[t] = add + x - v;
    if (t == 63) g_rowptr[n] = add + x;
    if (t == 0) {
        int run = 0;
        for (int i = 0; i < 64; i++) { g_dcur[i] = run; run += g_dhist[i]; }
    }
}

__global__ void scan3_kernel(int n) {
    int idx = blockIdx.x * blockDim.x + threadIdx.x;
    if (idx < n) {
        int r = g_rowptr[idx] + g_boff[idx >> 10];
        g_rowptr[idx] = r;
        g_cursor[idx] = r;
        int pos = atomicAdd(&g_dcur[min(g_deg[idx], 63)], 1);
        g_perm[pos] = idx;
    }
}

__global__ void scatter_kernel(const int* __restrict__ edges, int m) {
    int e = blockIdx.x * blockDim.x + threadIdx.x;
    if (e < m) {
        int d = edges[m + e];
        int pos = atomicAdd(&g_cursor[d], 1);
        g_colsrc[pos] = edges[e];
    }
}

// Sort each row's src list: deterministic accumulation order.
__global__ void sort_rows(int n) {
    int node = blockIdx.x * blockDim.x + threadIdx.x;
    if (node >= n) return;
    int s = g_rowptr[node], e = g_rowptr[node + 1];
    for (int i = s + 1; i < e; i++) {
        int v = g_colsrc[i];
        int j = i - 1;
        while (j >= s && g_colsrc[j] > v) { g_colsrc[j + 1] = g_colsrc[j]; j--; }
        g_colsrc[j + 1] = v;
    }
}

// ---------------------------------------------------------------------------
// unpack 6 bf16x2 words into 6 packed f32x2 regs (ALU-only conversion)
__device__ __forceinline__ void unpack6(uint4 a, uint2 b, u64* f) {
    f[0] = pk2(bflo(a.x), bfhi(a.x));
    f[1] = pk2(bflo(a.y), bfhi(a.y));
    f[2] = pk2(bflo(a.z), bfhi(a.z));
    f[3] = pk2(bflo(a.w), bfhi(a.w));
    f[4] = pk2(bflo(b.x), bfhi(b.x));
    f[5] = pk2(bflo(b.y), bfhi(b.y));
}

// load one smem entry: 16B chunk + 8B chunk (2 LDS, conflict-free) -> packed
__device__ __forceinline__ void ld_entry_p(const char* ebase, int lane, u64* f) {
    uint4 a = *(const uint4*)(ebase + lane * 16);
    uint2 b = *(const uint2*)(ebase + 512 + lane * 8);
    unpack6(a, b, f);
}

// packed dot: 6 FMA2 + reduce
__device__ __forceinline__ float dot12p(const u64* f, const u64* c2) {
    u64 t0 = mul2_(f[0], c2[0]);
    u64 t1 = mul2_(f[1], c2[1]);
    t0 = fma2_(f[2], c2[2], t0);
    t1 = fma2_(f[3], c2[3], t1);
    t0 = fma2_(f[4], c2[4], t0);
    t1 = fma2_(f[5], c2[5], t1);
    float2 h = upk2(add2_(t0, t1));
    return h.x + h.y;
}

// Persistent ALL-LAYERS routing kernel. One wave (592 blocks, 4/SM);
// device-side global barrier between layers. Per-WARP work stealing in
// 4-node chunks. bf16 gather buffer (ALU unpack, no F2F), packed f32x2
// dot+acc (halved FMA-pipe load), 2-edge unroll, pipelined overflow.
// Layers 0-2: z_next = l2norm(relu(c)) -> other buffer. Layer 3: relu(c) -> fout.
__global__ void __launch_bounds__(128, 4)
routing_all(__nv_bfloat16* __restrict__ zha, float* __restrict__ z32a,
            __nv_bfloat16* __restrict__ zhb, float* __restrict__ z32b,
            float* __restrict__ fout, int n) {
    extern __shared__ char sm[];
    int lane = threadIdx.x & 31;
    int warp = threadIdx.x >> 5;
    int group = lane >> 3;
    int cap = lane & 7;
    unsigned mask = 0xFFu << (group << 3);
    int nchunks = (n + 3) / 4;

    char* wslab = sm + warp * WSLAB;

    for (int layer = 0; layer < 4; layer++) {
        const __nv_bfloat16* zh_in = (layer & 1) ? zhb : zha;
        const float* z32_in  = (layer & 1) ? z32b : z32a;
        __nv_bfloat16* zh_out = (layer & 1) ? zha : zhb;
        float* z32_out       = (layer & 1) ? z32a : z32b;
        int last = (layer == 3);

        while (true) {
            int chunk;
            if (lane == 0) chunk = atomicAdd(&g_work[layer], 1);
            chunk = __shfl_sync(0xffffffffu, chunk, 0);
            if (chunk >= nchunks) break;

            int slot = chunk * 4 + group;
            bool valid = slot < n;
            int node = valid ? g_perm[(n - 1) - slot] : 0;   // descending degree

            int s = 0, deg = 0;
            if (valid) { s = g_rowptr[node]; deg = g_rowptr[node + 1] - s; }
            int cached = min(deg, CAP);

            // ---- fill: gather cached neighbor z rows, src prefetched ----
            {
                int e = 0;
                int src = (e < cached) ? g_colsrc[s + e] : 0;
                for (; e < cached; e++) {
                    int nsrc = (e + 1 < cached) ? g_colsrc[s + e + 1] : 0;
                    const uint2* gz = (const uint2*)(zh_in + (size_t)src * D) + cap * 3;
                    uint2 d0 = gz[0], d1 = gz[1], d2 = gz[2];
                    char* ebase = wslab + e * 768;
                    *(uint4*)(ebase + lane * 16) = make_uint4(d0.x, d0.y, d1.x, d1.y);
                    *(uint2*)(ebase + 512 + lane * 8) = d2;
                    src = nsrc;
                }
            }

            // ---- z_self (fp32); c init = z ----
            float z[12], c[12];
            u64 c2[6];
            if (valid) {
                const float4* zb = (const float4*)(z32_in + (size_t)node * D + cap * FAC);
                float4 a0 = zb[0], a1 = zb[1], a2 = zb[2];
                z[0] = a0.x; z[1] = a0.y; z[2]  = a0.z; z[3]  = a0.w;
                z[4] = a1.x; z[5] = a1.y; z[6]  = a1.z; z[7]  = a1.w;
                z[8] = a2.x; z[9] = a2.y; z[10] = a2.z; z[11] = a2.w;
#pragma unroll
                for (int i = 0; i < 12; i++) c[i] = z[i];
            } else {
#pragma unroll
                for (int i = 0; i < 12; i++) { z[i] = 0.f; c[i] = 0.f; }
            }
#pragma unroll
            for (int i = 0; i < 6; i++) c2[i] = pk2(c[2 * i], c[2 * i + 1]);
            __syncwarp();

            // ---- 6 routing iterations from smem / registers ----
            for (int it = 0; it < 6; it++) {
                u64 acc2[6];
#pragma unroll
                for (int i = 0; i < 6; i++) acc2[i] = 0ull;

                int e = 0;
                // 2-edge unrolled: two independent chains in flight
                for (; e + 1 < cached; e += 2) {
                    const char* p0 = wslab + e * 768;
                    u64 fA[6], fB[6];
                    ld_entry_p(p0,       lane, fA);
                    ld_entry_p(p0 + 768, lane, fB);
                    float exA = __expf(dot12p(fA, c2));
                    float exB = __expf(dot12p(fB, c2));
                    float sA = gsum8(exA, mask);
                    float sB = gsum8(exB, mask);
                    float pA = __fdividef(exA, sA);
                    float pB = __fdividef(exB, sB);
                    u64 pA2 = pk2(pA, pA);
                    u64 pB2 = pk2(pB, pB);
#pragma unroll
                    for (int i = 0; i < 6; i++) acc2[i] = fma2_(pA2, fA[i], acc2[i]);
#pragma unroll
                    for (int i = 0; i < 6; i++) acc2[i] = fma2_(pB2, fB[i], acc2[i]);
                }
                if (e < cached) {
                    const char* p0 = wslab + e * 768;
                    u64 fA[6];
                    ld_entry_p(p0, lane, fA);
                    float ex = __expf(dot12p(fA, c2));
                    float sm_ = gsum8(ex, mask);
                    float p = __fdividef(ex, sm_);
                    u64 p2 = pk2(p, p);
#pragma unroll
                    for (int i = 0; i < 6; i++) acc2[i] = fma2_(p2, fA[i], acc2[i]);
                }
                // overflow edges streamed from L2, software-pipelined
                {
                    int e2 = cached;
                    uint2 P0, P1, P2;
                    if (e2 < deg) {
                        const uint2* gz = (const uint2*)(zh_in + (size_t)g_colsrc[s + e2] * D + cap * FAC);
                        P0 = gz[0]; P1 = gz[1]; P2 = gz[2];
                    }
                    for (; e2 < deg; e2++) {
                        uint2 A0 = P0, A1 = P1, A2 = P2;
                        if (e2 + 1 < deg) {
                            const uint2* gz = (const uint2*)(zh_in + (size_t)g_colsrc[s + e2 + 1] * D + cap * FAC);
                            P0 = gz[0]; P1 = gz[1]; P2 = gz[2];
                        }
                        u64 fA[6];
                        unpack6(make_uint4(A0.x, A0.y, A1.x, A1.y), A2, fA);
                        float ex = __expf(dot12p(fA, c2));
                        float sm_ = gsum8(ex, mask);
                        float p = __fdividef(ex, sm_);
                        u64 p2 = pk2(p, p);
#pragma unroll
                        for (int i = 0; i < 6; i++) acc2[i] = fma2_(p2, fA[i], acc2[i]);
                    }
                }

                float v[12];
                float ss = 0.f;
#pragma unroll
                for (int i = 0; i < 6; i++) {
                    float2 h = upk2(acc2[i]);
                    v[2 * i]     = z[2 * i] + h.x;
                    v[2 * i + 1] = z[2 * i + 1] + h.y;
                    ss += v[2 * i] * v[2 * i] + v[2 * i + 1] * v[2 * i + 1];
                }
                float rn = rsqrtf(ss + 1e-12f);
#pragma unroll
                for (int i = 0; i < 12; i++) c[i] = v[i] * rn;
#pragma unroll
                for (int i = 0; i < 6; i++) c2[i] = pk2(c[2 * i], c[2 * i + 1]);
            }

            if (valid) {
#pragma unroll
                for (int i = 0; i < 12; i++) c[i] = fmaxf(c[i], 0.f);  // relu
                if (!last) {
                    float ss = 0.f;
#pragma unroll
                    for (int i = 0; i < 12; i++) ss += c[i] * c[i];
                    float rn = rsqrtf(ss + 1e-12f);
#pragma unroll
                    for (int i = 0; i < 12; i++) c[i] *= rn;
                    float4* zp = (float4*)(z32_out + (size_t)node * D + cap * FAC);
                    zp[0] = make_float4(c[0], c[1], c[2], c[3]);
                    zp[1] = make_float4(c[4], c[5], c[6], c[7]);
                    zp[2] = make_float4(c[8], c[9], c[10], c[11]);
                    uint2* zh = (uint2*)(zh_out + (size_t)node * D + cap * FAC);
                    __nv_bfloat162 b0 = __floats2bfloat162_rn(c[0], c[1]);
                    __nv_bfloat162 b1 = __floats2bfloat162_rn(c[2], c[3]);
                    __nv_bfloat162 b2 = __floats2bfloat162_rn(c[4], c[5]);
                    __nv_bfloat162 b3 = __floats2bfloat162_rn(c[6], c[7]);
                    __nv_bfloat162 b4 = __floats2bfloat162_rn(c[8], c[9]);
                    __nv_bfloat162 b5 = __floats2bfloat162_rn(c[10], c[11]);
                    zh[0] = make_uint2(*(unsigned*)&b0, *(unsigned*)&b1);
                    zh[1] = make_uint2(*(unsigned*)&b2, *(unsigned*)&b3);
                    zh[2] = make_uint2(*(unsigned*)&b4, *(unsigned*)&b5);
                } else {
                    float4* fo = (float4*)(fout + (size_t)node * D + cap * FAC);
                    fo[0] = make_float4(c[0], c[1], c[2], c[3]);
                    fo[1] = make_float4(c[4], c[5], c[6], c[7]);
                    fo[2] = make_float4(c[8], c[9], c[10], c[11]);
                }
            }
        }

        if (layer < 3) {
            // global barrier: release writes, arrive, spin until all arrive
            __syncthreads();
            if (threadIdx.x == 0) {
                __threadfence();
                atomicAdd(&g_bar[layer], 1);
                while (((volatile int*)g_bar)[layer] < gridDim.x) { }
            }
            __syncthreads();
            __threadfence();
        }
    }
}

// ---------------------------------------------------------------------------
extern "C" void kernel_launch(void* const* d_in, const int* in_sizes, int n_in,
                              void* d_out, int out_size) {
    const float* X     = (const float*)d_in[0];
    const int*   edges = (const int*)d_in[1];
    const float* W     = (const float*)d_in[2];
    const float* b     = (const float*)d_in[3];
    int n = in_sizes[0] / 256;   // 50000
    int m = in_sizes[1] / 2;     // 800000

    cudaFuncSetAttribute(routing_all,
                         cudaFuncAttributeMaxDynamicSharedMemorySize, ROUTE_SMEM);

    __nv_bfloat16* zha; cudaGetSymbolAddress((void**)&zha, g_zh_a);
    __nv_bfloat16* zhb; cudaGetSymbolAddress((void**)&zhb, g_zh_b);
    float* z32a; cudaGetSymbolAddress((void**)&z32a, g_z32_a);
    float* z32b; cudaGetSymbolAddress((void**)&z32b, g_z32_b);

    // zero + W transpose + counter reset, then init+prep fused
    zero_wt_kernel<<<(n + 255) / 256, 256>>>(W, n);
    init_gemm<<<(n + 31) / 32, 96>>>(X, b, n);

    // CSR by dst (deterministic: rows sorted by src); perm fused into scans
    hist_kernel<<<(m + 255) / 256, 256>>>(edges, m);
    int sblocks = (n + 1023) / 1024;   // 49 <= 64
    scan1_kernel<<<sblocks, 1024>>>(n);
    scan2_kernel<<<1, 64>>>(sblocks, n);
    scan3_kernel<<<(n + 255) / 256, 256>>>(n);
    scatter_kernel<<<(m + 255) / 256, 256>>>(edges, m);
    sort_rows<<<(n + 255) / 256, 256>>>(n);

    // single persistent kernel: all 4 routing layers with device barriers
    routing_all<<<ROUTE_GRID, 128, ROUTE_SMEM>>>(zha, z32a, zhb, z32b,
                                                 (float*)d_out, n);
}

// round 15
// speedup vs baseline: 1.1006x; 1.1006x over previous
#include <cuda_runtime.h>
#include <cuda_fp16.h>

// Problem constants (fixed shapes)
#define N_MAX 50000
#define M_MAX 800000
#define D 96          // K*FAC
#define KCAP 8
#define FAC 12

#define CAP 18                        // cached neighbors per node in smem (fp16)
#define WSLAB (CAP * 768)             // per-warp slab: CAP entries x 768B
#define ROUTE_SMEM (4 * WSLAB)        // 55296 B per 128-thread block -> 4 blocks/SM
#define ROUTE_GRID 592                // 148 SMs x 4 resident blocks: exactly one wave

typedef unsigned long long u64;

// Static scratch (no allocations allowed)
__device__ __half g_zh_a[N_MAX * D];   // fp16 z double-buffer A (gather source)
__device__ __half g_zh_b[N_MAX * D];   // fp16 z double-buffer B
__device__ float  g_z32_a[N_MAX * D];  // fp32 z double-buffer A (self-term)
__device__ float  g_z32_b[N_MAX * D];  // fp32 z double-buffer B
__device__ float  g_wt[D * 256];       // W transposed to [out=96][in=256]
__device__ int    g_deg[N_MAX];
__device__ int    g_rowptr[N_MAX + 1];
__device__ int    g_cursor[N_MAX];
__device__ int    g_colsrc[M_MAX];
__device__ int    g_bsum[64];
__device__ int    g_boff[64];
__device__ int    g_dhist[64];
__device__ int    g_dcur[64];
__device__ int    g_perm[N_MAX];
__device__ int    g_work[4];           // per-layer work-stealing counters
__device__ int    g_bar[4];            // per-layer global barrier counters

// ---------------- packed f32x2 helpers (init GEMM only) --------------------
__device__ __forceinline__ u64 pk2(float lo, float hi) {
    u64 r; asm("mov.b64 %0,{%1,%2};" : "=l"(r) : "f"(lo), "f"(hi)); return r;
}
__device__ __forceinline__ float2 upk2(u64 v) {
    float2 f; asm("mov.b64 {%0,%1},%2;" : "=f"(f.x), "=f"(f.y) : "l"(v)); return f;
}
__device__ __forceinline__ u64 fma2_(u64 a, u64 b, u64 c) {
    u64 d; asm("fma.rn.f32x2 %0,%1,%2,%3;" : "=l"(d) : "l"(a), "l"(b), "l"(c)); return d;
}

// 8-lane group sum (3-shuffle butterfly; fp32 redux unsupported on sm_103)
__device__ __forceinline__ float gsum8(float v, unsigned mask) {
    v += __shfl_xor_sync(mask, v, 1);
    v += __shfl_xor_sync(mask, v, 2);
    v += __shfl_xor_sync(mask, v, 4);
    return v;
}

// ---------------------------------------------------------------------------
// zero + W transpose fused; also resets work/barrier counters each replay.
__global__ void zero_wt_kernel(const float* __restrict__ W, int n) {
    int i = blockIdx.x * blockDim.x + threadIdx.x;
    if (i < n) g_deg[i] = 0;
    if (i < 64) g_dhist[i] = 0;
    if (i < 4) { g_work[i] = 0; g_bar[i] = 0; }
    if (i < D * 256) {
        int o = i >> 8, c = i & 255;
        int k = o / FAC, oo = o % FAC;
        g_wt[i] = W[k * (256 * FAC) + c * FAC + oo];
    }
}

// ---------------------------------------------------------------------------
// Init layer fused with prep: Z = relu(X.Wt + b) staged in smem, then
// z = l2norm(Z) written to z32_a (fp32) + zh_a (fp16). f32x2 FMA mainloop.
__global__ void __launch_bounds__(96) init_gemm(const float* __restrict__ X,
                                                const float* __restrict__ bv, int n) {
    __shared__ float xs[32][256];
    __shared__ float os[32][96];
    int t = threadIdx.x;
    int nb = blockIdx.x * 32;
    for (int j = t; j < 32 * 256; j += 96) {
        int q = j >> 8;
        xs[q][j & 255] = (nb + q < n) ? X[nb * 256 + j] : 0.f;
    }
    __syncthreads();

    u64 acc[32];
#pragma unroll
    for (int q = 0; q < 32; q++) acc[q] = 0ull;

    const float4* wrow = (const float4*)(g_wt + t * 256);
#pragma unroll 2
    for (int i4 = 0; i4 < 64; i4++) {
        float4 w = wrow[i4];
        u64 w01 = pk2(w.x, w.y);
        u64 w23 = pk2(w.z, w.w);
#pragma unroll
        for (int q = 0; q < 32; q++) {
            float4 xv = *(const float4*)&xs[q][i4 * 4];
            acc[q] = fma2_(w01, pk2(xv.x, xv.y), acc[q]);
            acc[q] = fma2_(w23, pk2(xv.z, xv.w), acc[q]);
        }
    }
    float bb = bv[t];
#pragma unroll
    for (int q = 0; q < 32; q++) {
        float2 h = upk2(acc[q]);
        os[q][t] = fmaxf(h.x + h.y + bb, 0.f);   // relu(Z)
    }
    __syncthreads();

    // prep: per (node, capsule) l2norm -> z32_a + zh_a (fp16)
    for (int idx = t; idx < 32 * KCAP; idx += 96) {
        int q = idx >> 3, cp = idx & 7;
        if (nb + q >= n) continue;
        const float* r = &os[q][cp * FAC];
        float v[12];
        float s = 0.f;
#pragma unroll
        for (int i = 0; i < 12; i++) { v[i] = r[i]; s += v[i] * v[i]; }
        float rn = rsqrtf(s + 1e-12f);
#pragma unroll
        for (int i = 0; i < 12; i++) v[i] *= rn;
        int gi = ((nb + q) * KCAP + cp) * FAC;
        float4* zp = (float4*)(g_z32_a + gi);
        zp[0] = make_float4(v[0], v[1], v[2], v[3]);
        zp[1] = make_float4(v[4], v[5], v[6], v[7]);
        zp[2] = make_float4(v[8], v[9], v[10], v[11]);
        uint2* zh = (uint2*)(g_zh_a + gi);
        __half2 h0 = __floats2half2_rn(v[0], v[1]);
        __half2 h1 = __floats2half2_rn(v[2], v[3]);
        __half2 h2 = __floats2half2_rn(v[4], v[5]);
        __half2 h3 = __floats2half2_rn(v[6], v[7]);
        __half2 h4 = __floats2half2_rn(v[8], v[9]);
        __half2 h5 = __floats2half2_rn(v[10], v[11]);
        zh[0] = make_uint2(*(unsigned*)&h0, *(unsigned*)&h1);
        zh[1] = make_uint2(*(unsigned*)&h2, *(unsigned*)&h3);
        zh[2] = make_uint2(*(unsigned*)&h4, *(unsigned*)&h5);
    }
}

// ---------------------------------------------------------------------------
// CSR build: hist -> 3-phase hierarchical scan (with perm stages fused)
__global__ void hist_kernel(const int* __restrict__ edges, int m) {
    int e = blockIdx.x * blockDim.x + threadIdx.x;
    if (e < m) atomicAdd(&g_deg[edges[m + e]], 1);
}

__global__ void scan1_kernel(int n) {
    __shared__ int wsum[32];
    __shared__ int h[64];
    int t = threadIdx.x, lane = t & 31, wid = t >> 5;
    if (t < 64) h[t] = 0;
    int idx = blockIdx.x * 1024 + t;
    int v = (idx < n) ? g_deg[idx] : 0;
    int x = v;
#pragma unroll
    for (int off = 1; off < 32; off <<= 1) {
        int y = __shfl_up_sync(0xffffffffu, x, off);
        if (lane >= off) x += y;
    }
    if (lane == 31) wsum[wid] = x;
    __syncthreads();
    if (wid == 0) {
        int w = wsum[lane];
#pragma unroll
        for (int off = 1; off < 32; off <<= 1) {
            int y = __shfl_up_sync(0xffffffffu, w, off);
            if (lane >= off) w += y;
        }
        wsum[lane] = w;
    }
    if (idx < n) atomicAdd(&h[min(v, 63)], 1);
    __syncthreads();
    int pre = (wid > 0) ? wsum[wid - 1] : 0;
    if (idx < n) g_rowptr[idx] = pre + x - v;   // block-local exclusive
    if (t == 1023) g_bsum[blockIdx.x] = pre + x;
    if (t < 64 && h[t]) atomicAdd(&g_dhist[t], h[t]);
}

__global__ void scan2_kernel(int nblocks, int n) {
    int t = threadIdx.x;  // 64 threads
    int v = (t < nblocks) ? g_bsum[t] : 0;
    int x = v;
    int lane = t & 31, wid = t >> 5;
    __shared__ int ws[2];
#pragma unroll
    for (int off = 1; off < 32; off <<= 1) {
        int y = __shfl_up_sync(0xffffffffu, x, off);
        if (lane >= off) x += y;
    }
    if (lane == 31) ws[wid] = x;
    __syncthreads();
    int add = (wid == 1) ? ws[0] : 0;
    g_boff[t] = add + x - v;
    if (t == 63) g_rowptr[n] = add + x;
    if (t == 0) {
        int run = 0;
        for (int i = 0; i < 64; i++) { g_dcur[i] = run; run += g_dhist[i]; }
    }
}

__global__ void scan3_kernel(int n) {
    int idx = blockIdx.x * blockDim.x + threadIdx.x;
    if (idx < n) {
        int r = g_rowptr[idx] + g_boff[idx >> 10];
        g_rowptr[idx] = r;
        g_cursor[idx] = r;
        int pos = atomicAdd(&g_dcur[min(g_deg[idx], 63)], 1);
        g_perm[pos] = idx;
    }
}

__global__ void scatter_kernel(const int* __restrict__ edges, int m) {
    int e = blockIdx.x * blockDim.x + threadIdx.x;
    if (e < m) {
        int d = edges[m + e];
        int pos = atomicAdd(&g_cursor[d], 1);
        g_colsrc[pos] = edges[e];
    }
}

// Sort each row's src list: deterministic accumulation order.
__global__ void sort_rows(int n) {
    int node = blockIdx.x * blockDim.x + threadIdx.x;
    if (node >= n) return;
    int s = g_rowptr[node], e = g_rowptr[node + 1];
    for (int i = s + 1; i < e; i++) {
        int v = g_colsrc[i];
        int j = i - 1;
        while (j >= s && g_colsrc[j] > v) { g_colsrc[j + 1] = g_colsrc[j]; j--; }
        g_colsrc[j + 1] = v;
    }
}

// ---------------------------------------------------------------------------
// half2 views of a 16B+8B smem entry
__device__ __forceinline__ __half2 h2of(unsigned u) { return *(__half2*)&u; }

// dot of one edge (6 half2 words) against c (half2): HFMA2 chain, no cvt
__device__ __forceinline__ float dot12h(uint4 a, uint2 b, const __half2* ch) {
    __half2 d0 = __hmul2(h2of(a.x), ch[0]);
    __half2 d1 = __hmul2(h2of(a.y), ch[1]);
    d0 = __hfma2(h2of(a.z), ch[2], d0);
    d1 = __hfma2(h2of(a.w), ch[3], d1);
    d0 = __hfma2(h2of(b.x), ch[4], d0);
    d1 = __hfma2(h2of(b.y), ch[5], d1);
    float2 t = __half22float2(__hadd2(d0, d1));
    return t.x + t.y;
}

// acc_h[i] += p2 * edge[i]   (6 HFMA2)
__device__ __forceinline__ void acc12h(uint4 a, uint2 b, __half2 p2, __half2* acc_h) {
    acc_h[0] = __hfma2(p2, h2of(a.x), acc_h[0]);
    acc_h[1] = __hfma2(p2, h2of(a.y), acc_h[1]);
    acc_h[2] = __hfma2(p2, h2of(a.z), acc_h[2]);
    acc_h[3] = __hfma2(p2, h2of(a.w), acc_h[3]);
    acc_h[4] = __hfma2(p2, h2of(b.x), acc_h[4]);
    acc_h[5] = __hfma2(p2, h2of(b.y), acc_h[5]);
}

// Persistent ALL-LAYERS routing kernel. One wave (592 blocks, 4/SM);
// device-side global barrier between layers; per-WARP work stealing in
// 4-node chunks. Full half2 inner loop: dot AND accumulate run as
// HFMA2/HADD2 directly on the fp16 smem words (no per-edge conversions);
// softmax sum/div stay fp32; acc converted to fp32 once per iteration.
// Layers 0-2: z_next = l2norm(relu(c)) -> other buffer. Layer 3: relu(c) -> fout.
__global__ void __launch_bounds__(128, 4)
routing_all(__half* __restrict__ zha, float* __restrict__ z32a,
            __half* __restrict__ zhb, float* __restrict__ z32b,
            float* __restrict__ fout, int n) {
    extern __shared__ char sm[];
    int lane = threadIdx.x & 31;
    int warp = threadIdx.x >> 5;
    int group = lane >> 3;
    int cap = lane & 7;
    unsigned mask = 0xFFu << (group << 3);
    int nchunks = (n + 3) / 4;

    char* wslab = sm + warp * WSLAB;

    for (int layer = 0; layer < 4; layer++) {
        const __half* zh_in  = (layer & 1) ? zhb : zha;
        const float* z32_in  = (layer & 1) ? z32b : z32a;
        __half* zh_out       = (layer & 1) ? zha : zhb;
        float* z32_out       = (layer & 1) ? z32a : z32b;
        int last = (layer == 3);

        while (true) {
            int chunk;
            if (lane == 0) chunk = atomicAdd(&g_work[layer], 1);
            chunk = __shfl_sync(0xffffffffu, chunk, 0);
            if (chunk >= nchunks) break;

            int slot = chunk * 4 + group;
            bool valid = slot < n;
            int node = valid ? g_perm[(n - 1) - slot] : 0;   // descending degree

            int s = 0, deg = 0;
            if (valid) { s = g_rowptr[node]; deg = g_rowptr[node + 1] - s; }
            int cached = min(deg, CAP);

            // ---- fill: gather cached neighbor z rows, src prefetched ----
            {
                int e = 0;
                int src = (e < cached) ? g_colsrc[s + e] : 0;
                for (; e < cached; e++) {
                    int nsrc = (e + 1 < cached) ? g_colsrc[s + e + 1] : 0;
                    const uint2* gz = (const uint2*)(zh_in + (size_t)src * D) + cap * 3;
                    uint2 d0 = gz[0], d1 = gz[1], d2 = gz[2];
                    char* ebase = wslab + e * 768;
                    *(uint4*)(ebase + lane * 16) = make_uint4(d0.x, d0.y, d1.x, d1.y);
                    *(uint2*)(ebase + 512 + lane * 8) = d2;
                    src = nsrc;
                }
            }

            // ---- z_self (fp32); c init = z ----
            float z[12], c[12];
            __half2 ch[6];
            if (valid) {
                const float4* zb = (const float4*)(z32_in + (size_t)node * D + cap * FAC);
                float4 a0 = zb[0], a1 = zb[1], a2 = zb[2];
                z[0] = a0.x; z[1] = a0.y; z[2]  = a0.z; z[3]  = a0.w;
                z[4] = a1.x; z[5] = a1.y; z[6]  = a1.z; z[7]  = a1.w;
                z[8] = a2.x; z[9] = a2.y; z[10] = a2.z; z[11] = a2.w;
            } else {
#pragma unroll
                for (int i = 0; i < 12; i++) z[i] = 0.f;
            }
#pragma unroll
            for (int i = 0; i < 12; i++) c[i] = z[i];
#pragma unroll
            for (int i = 0; i < 6; i++) ch[i] = __floats2half2_rn(c[2 * i], c[2 * i + 1]);
            __syncwarp();

            // ---- 6 routing iterations, half2 math from smem ----
            for (int it = 0; it < 6; it++) {
                __half2 acc_h[6];
#pragma unroll
                for (int i = 0; i < 6; i++) acc_h[i] = __floats2half2_rn(0.f, 0.f);

                int e = 0;
                // 4-edge unrolled: four independent chains in flight
                for (; e + 3 < cached; e += 4) {
                    const char* p0 = wslab + e * 768;
                    uint4 A0 = *(const uint4*)(p0 + lane * 16);
                    uint2 B0 = *(const uint2*)(p0 + 512 + lane * 8);
                    uint4 A1 = *(const uint4*)(p0 + 768 + lane * 16);
                    uint2 B1 = *(const uint2*)(p0 + 768 + 512 + lane * 8);
                    uint4 A2 = *(const uint4*)(p0 + 1536 + lane * 16);
                    uint2 B2 = *(const uint2*)(p0 + 1536 + 512 + lane * 8);
                    uint4 A3 = *(const uint4*)(p0 + 2304 + lane * 16);
                    uint2 B3 = *(const uint2*)(p0 + 2304 + 512 + lane * 8);
                    float ex0 = __expf(dot12h(A0, B0, ch));
                    float ex1 = __expf(dot12h(A1, B1, ch));
                    float ex2 = __expf(dot12h(A2, B2, ch));
                    float ex3 = __expf(dot12h(A3, B3, ch));
                    float s0 = gsum8(ex0, mask);
                    float s1 = gsum8(ex1, mask);
                    float s2 = gsum8(ex2, mask);
                    float s3 = gsum8(ex3, mask);
                    __half2 p0h = __float2half2_rn(__fdividef(ex0, s0));
                    __half2 p1h = __float2half2_rn(__fdividef(ex1, s1));
                    __half2 p2h = __float2half2_rn(__fdividef(ex2, s2));
                    __half2 p3h = __float2half2_rn(__fdividef(ex3, s3));
                    acc12h(A0, B0, p0h, acc_h);
                    acc12h(A1, B1, p1h, acc_h);
                    acc12h(A2, B2, p2h, acc_h);
                    acc12h(A3, B3, p3h, acc_h);
                }
                for (; e < cached; e++) {
                    const char* p0 = wslab + e * 768;
                    uint4 A0 = *(const uint4*)(p0 + lane * 16);
                    uint2 B0 = *(const uint2*)(p0 + 512 + lane * 8);
                    float ex = __expf(dot12h(A0, B0, ch));
                    float sm_ = gsum8(ex, mask);
                    __half2 ph = __float2half2_rn(__fdividef(ex, sm_));
                    acc12h(A0, B0, ph, acc_h);
                }
                // overflow edges streamed from L2, software-pipelined
                {
                    int e2 = cached;
                    uint2 P0, P1, P2;
                    if (e2 < deg) {
                        const uint2* gz = (const uint2*)(zh_in + (size_t)g_colsrc[s + e2] * D + cap * FAC);
                        P0 = gz[0]; P1 = gz[1]; P2 = gz[2];
                    }
                    for (; e2 < deg; e2++) {
                        uint2 Q0 = P0, Q1 = P1, Q2 = P2;
                        if (e2 + 1 < deg) {
                            const uint2* gz = (const uint2*)(zh_in + (size_t)g_colsrc[s + e2 + 1] * D + cap * FAC);
                            P0 = gz[0]; P1 = gz[1]; P2 = gz[2];
                        }
                        uint4 A = make_uint4(Q0.x, Q0.y, Q1.x, Q1.y);
                        float ex = __expf(dot12h(A, Q2, ch));
                        float sm_ = gsum8(ex, mask);
                        __half2 ph = __float2half2_rn(__fdividef(ex, sm_));
                        acc12h(A, Q2, ph, acc_h);
                    }
                }

                // v = z + float(acc); c = l2norm(v)
                float v[12];
                float ss = 0.f;
#pragma unroll
                for (int i = 0; i < 6; i++) {
                    float2 h = __half22float2(acc_h[i]);
                    v[2 * i]     = z[2 * i] + h.x;
                    v[2 * i + 1] = z[2 * i + 1] + h.y;
                    ss += v[2 * i] * v[2 * i] + v[2 * i + 1] * v[2 * i + 1];
                }
                float rn = rsqrtf(ss + 1e-12f);
#pragma unroll
                for (int i = 0; i < 12; i++) c[i] = v[i] * rn;
#pragma unroll
                for (int i = 0; i < 6; i++) ch[i] = __floats2half2_rn(c[2 * i], c[2 * i + 1]);
            }

            if (valid) {
#pragma unroll
                for (int i = 0; i < 12; i++) c[i] = fmaxf(c[i], 0.f);  // relu
                if (!last) {
                    float ss = 0.f;
#pragma unroll
                    for (int i = 0; i < 12; i++) ss += c[i] * c[i];
                    float rn = rsqrtf(ss + 1e-12f);
#pragma unroll
                    for (int i = 0; i < 12; i++) c[i] *= rn;
                    float4* zp = (float4*)(z32_out + (size_t)node * D + cap * FAC);
                    zp[0] = make_float4(c[0], c[1], c[2], c[3]);
                    zp[1] = make_float4(c[4], c[5], c[6], c[7]);
                    zp[2] = make_float4(c[8], c[9], c[10], c[11]);
                    uint2* zh = (uint2*)(zh_out + (size_t)node * D + cap * FAC);
                    __half2 h0 = __floats2half2_rn(c[0], c[1]);
                    __half2 h1 = __floats2half2_rn(c[2], c[3]);
                    __half2 h2 = __floats2half2_rn(c[4], c[5]);
                    __half2 h3 = __floats2half2_rn(c[6], c[7]);
                    __half2 h4 = __floats2half2_rn(c[8], c[9]);
                    __half2 h5 = __floats2half2_rn(c[10], c[11]);
                    zh[0] = make_uint2(*(unsigned*)&h0, *(unsigned*)&h1);
                    zh[1] = make_uint2(*(unsigned*)&h2, *(unsigned*)&h3);
                    zh[2] = make_uint2(*(unsigned*)&h4, *(unsigned*)&h5);
                } else {
                    float4* fo = (float4*)(fout + (size_t)node * D + cap * FAC);
                    fo[0] = make_float4(c[0], c[1], c[2], c[3]);
                    fo[1] = make_float4(c[4], c[5], c[6], c[7]);
                    fo[2] = make_float4(c[8], c[9], c[10], c[11]);
                }
            }
        }

        if (layer < 3) {
            // global barrier: release writes, arrive, spin until all arrive
            __syncthreads();
            if (threadIdx.x == 0) {
                __threadfence();
                atomicAdd(&g_bar[layer], 1);
                while (((volatile int*)g_bar)[layer] < gridDim.x) { }
            }
            __syncthreads();
            __threadfence();
        }
    }
}

// ---------------------------------------------------------------------------
extern "C" void kernel_launch(void* const* d_in, const int* in_sizes, int n_in,
                              void* d_out, int out_size) {
    const float* X     = (const float*)d_in[0];
    const int*   edges = (const int*)d_in[1];
    const float* W     = (const float*)d_in[2];
    const float* b     = (const float*)d_in[3];
    int n = in_sizes[0] / 256;   // 50000
    int m = in_sizes[1] / 2;     // 800000

    cudaFuncSetAttribute(routing_all,
                         cudaFuncAttributeMaxDynamicSharedMemorySize, ROUTE_SMEM);

    __half* zha; cudaGetSymbolAddress((void**)&zha, g_zh_a);
    __half* zhb; cudaGetSymbolAddress((void**)&zhb, g_zh_b);
    float* z32a; cudaGetSymbolAddress((void**)&z32a, g_z32_a);
    float* z32b; cudaGetSymbolAddress((void**)&z32b, g_z32_b);

    // zero + W transpose + counter reset, then init+prep fused
    zero_wt_kernel<<<(n + 255) / 256, 256>>>(W, n);
    init_gemm<<<(n + 31) / 32, 96>>>(X, b, n);

    // CSR by dst (deterministic: rows sorted by src); perm fused into scans
    hist_kernel<<<(m + 255) / 256, 256>>>(edges, m);
    int sblocks = (n + 1023) / 1024;   // 49 <= 64
    scan1_kernel<<<sblocks, 1024>>>(n);
    scan2_kernel<<<1, 64>>>(sblocks, n);
    scan3_kernel<<<(n + 255) / 256, 256>>>(n);
    scatter_kernel<<<(m + 255) / 256, 256>>>(edges, m);
    sort_rows<<<(n + 255) / 256, 256>>>(n);

    // single persistent kernel: all 4 routing layers with device barriers
    routing_all<<<ROUTE_GRID, 128, ROUTE_SMEM>>>(zha, z32a, zhb, z32b,
                                                 (float*)d_out, n);
}

// round 16
// speedup vs baseline: 1.1538x; 1.0483x over previous
#include <cuda_runtime.h>
#include <cuda_fp16.h>

// Problem constants (fixed shapes)
#define N_MAX 50000
#define M_MAX 800000
#define D 96          // K*FAC
#define KCAP 8
#define FAC 12

#define CAP 18                        // cached neighbors per node in smem (fp16)
#define WSLAB (CAP * 768)             // per-warp slab: CAP entries x 768B
#define ROUTE_SMEM (4 * WSLAB)        // 55296 B per 128-thread block -> 4 blocks/SM
#define ROUTE_GRID 592                // 148 SMs x 4 resident blocks: exactly one wave

typedef unsigned long long u64;

// Static scratch (no allocations allowed)
__device__ __half g_zh_a[N_MAX * D];   // fp16 z double-buffer A (gather source)
__device__ __half g_zh_b[N_MAX * D];   // fp16 z double-buffer B
__device__ float  g_z32_a[N_MAX * D];  // fp32 z double-buffer A (self-term)
__device__ float  g_z32_b[N_MAX * D];  // fp32 z double-buffer B
__device__ float  g_wt[D * 256];       // W transposed to [out=96][in=256]
__device__ int    g_deg[N_MAX];
__device__ int    g_rowptr[N_MAX + 1];
__device__ int    g_cursor[N_MAX];
__device__ int    g_colsrc[M_MAX];
__device__ int    g_bsum[64];
__device__ int    g_boff[64];
__device__ int    g_dhist[64];
__device__ int    g_dcur[64];
__device__ int    g_perm[N_MAX];
__device__ int    g_work[4];           // per-layer work-stealing counters
__device__ int    g_bar[4];            // per-layer global barrier counters

// ---------------- packed f32x2 helpers (init GEMM only) --------------------
__device__ __forceinline__ u64 pk2(float lo, float hi) {
    u64 r; asm("mov.b64 %0,{%1,%2};" : "=l"(r) : "f"(lo), "f"(hi)); return r;
}
__device__ __forceinline__ float2 upk2(u64 v) {
    float2 f; asm("mov.b64 {%0,%1},%2;" : "=f"(f.x), "=f"(f.y) : "l"(v)); return f;
}
__device__ __forceinline__ u64 fma2_(u64 a, u64 b, u64 c) {
    u64 d; asm("fma.rn.f32x2 %0,%1,%2,%3;" : "=l"(d) : "l"(a), "l"(b), "l"(c)); return d;
}

// 8-lane group sum, fp32 (solo-edge path)
__device__ __forceinline__ float gsum8(float v, unsigned mask) {
    v += __shfl_xor_sync(mask, v, 1);
    v += __shfl_xor_sync(mask, v, 2);
    v += __shfl_xor_sync(mask, v, 4);
    return v;
}

// 8-lane group sum of an (ex0, ex1) pair packed in half2: one butterfly for 2 edges
__device__ __forceinline__ __half2 hsum8(__half2 v, unsigned mask) {
    unsigned u = *(unsigned*)&v, r;
    r = __shfl_xor_sync(mask, u, 1); v = __hadd2(v, *(__half2*)&r); u = *(unsigned*)&v;
    r = __shfl_xor_sync(mask, u, 2); v = __hadd2(v, *(__half2*)&r); u = *(unsigned*)&v;
    r = __shfl_xor_sync(mask, u, 4); v = __hadd2(v, *(__half2*)&r);
    return v;
}

// ---------------------------------------------------------------------------
// zero + W transpose fused; also resets work/barrier counters each replay.
__global__ void zero_wt_kernel(const float* __restrict__ W, int n) {
    int i = blockIdx.x * blockDim.x + threadIdx.x;
    if (i < n) g_deg[i] = 0;
    if (i < 64) g_dhist[i] = 0;
    if (i < 4) { g_work[i] = 0; g_bar[i] = 0; }
    if (i < D * 256) {
        int o = i >> 8, c = i & 255;
        int k = o / FAC, oo = o % FAC;
        g_wt[i] = W[k * (256 * FAC) + c * FAC + oo];
    }
}

// ---------------------------------------------------------------------------
// Init layer fused with prep: Z = relu(X.Wt + b) staged in smem, then
// z = l2norm(Z) written to z32_a (fp32) + zh_a (fp16). f32x2 FMA mainloop.
__global__ void __launch_bounds__(96) init_gemm(const float* __restrict__ X,
                                                const float* __restrict__ bv, int n) {
    __shared__ float xs[32][256];
    __shared__ float os[32][96];
    int t = threadIdx.x;
    int nb = blockIdx.x * 32;
    for (int j = t; j < 32 * 256; j += 96) {
        int q = j >> 8;
        xs[q][j & 255] = (nb + q < n) ? X[nb * 256 + j] : 0.f;
    }
    __syncthreads();

    u64 acc[32];
#pragma unroll
    for (int q = 0; q < 32; q++) acc[q] = 0ull;

    const float4* wrow = (const float4*)(g_wt + t * 256);
#pragma unroll 2
    for (int i4 = 0; i4 < 64; i4++) {
        float4 w = wrow[i4];
        u64 w01 = pk2(w.x, w.y);
        u64 w23 = pk2(w.z, w.w);
#pragma unroll
        for (int q = 0; q < 32; q++) {
            float4 xv = *(const float4*)&xs[q][i4 * 4];
            acc[q] = fma2_(w01, pk2(xv.x, xv.y), acc[q]);
            acc[q] = fma2_(w23, pk2(xv.z, xv.w), acc[q]);
        }
    }
    float bb = bv[t];
#pragma unroll
    for (int q = 0; q < 32; q++) {
        float2 h = upk2(acc[q]);
        os[q][t] = fmaxf(h.x + h.y + bb, 0.f);   // relu(Z)
    }
    __syncthreads();

    // prep: per (node, capsule) l2norm -> z32_a + zh_a (fp16)
    for (int idx = t; idx < 32 * KCAP; idx += 96) {
        int q = idx >> 3, cp = idx & 7;
        if (nb + q >= n) continue;
        const float* r = &os[q][cp * FAC];
        float v[12];
        float s = 0.f;
#pragma unroll
        for (int i = 0; i < 12; i++) { v[i] = r[i]; s += v[i] * v[i]; }
        float rn = rsqrtf(s + 1e-12f);
#pragma unroll
        for (int i = 0; i < 12; i++) v[i] *= rn;
        int gi = ((nb + q) * KCAP + cp) * FAC;
        float4* zp = (float4*)(g_z32_a + gi);
        zp[0] = make_float4(v[0], v[1], v[2], v[3]);
        zp[1] = make_float4(v[4], v[5], v[6], v[7]);
        zp[2] = make_float4(v[8], v[9], v[10], v[11]);
        uint2* zh = (uint2*)(g_zh_a + gi);
        __half2 h0 = __floats2half2_rn(v[0], v[1]);
        __half2 h1 = __floats2half2_rn(v[2], v[3]);
        __half2 h2 = __floats2half2_rn(v[4], v[5]);
        __half2 h3 = __floats2half2_rn(v[6], v[7]);
        __half2 h4 = __floats2half2_rn(v[8], v[9]);
        __half2 h5 = __floats2half2_rn(v[10], v[11]);
        zh[0] = make_uint2(*(unsigned*)&h0, *(unsigned*)&h1);
        zh[1] = make_uint2(*(unsigned*)&h2, *(unsigned*)&h3);
        zh[2] = make_uint2(*(unsigned*)&h4, *(unsigned*)&h5);
    }
}

// ---------------------------------------------------------------------------
// CSR build: hist -> 3-phase hierarchical scan (with perm stages fused)
__global__ void hist_kernel(const int* __restrict__ edges, int m) {
    int e = blockIdx.x * blockDim.x + threadIdx.x;
    if (e < m) atomicAdd(&g_deg[edges[m + e]], 1);
}

__global__ void scan1_kernel(int n) {
    __shared__ int wsum[32];
    __shared__ int h[64];
    int t = threadIdx.x, lane = t & 31, wid = t >> 5;
    if (t < 64) h[t] = 0;
    int idx = blockIdx.x * 1024 + t;
    int v = (idx < n) ? g_deg[idx] : 0;
    int x = v;
#pragma unroll
    for (int off = 1; off < 32; off <<= 1) {
        int y = __shfl_up_sync(0xffffffffu, x, off);
        if (lane >= off) x += y;
    }
    if (lane == 31) wsum[wid] = x;
    __syncthreads();
    if (wid == 0) {
        int w = wsum[lane];
#pragma unroll
        for (int off = 1; off < 32; off <<= 1) {
            int y = __shfl_up_sync(0xffffffffu, w, off);
            if (lane >= off) w += y;
        }
        wsum[lane] = w;
    }
    if (idx < n) atomicAdd(&h[min(v, 63)], 1);
    __syncthreads();
    int pre = (wid > 0) ? wsum[wid - 1] : 0;
    if (idx < n) g_rowptr[idx] = pre + x - v;   // block-local exclusive
    if (t == 1023) g_bsum[blockIdx.x] = pre + x;
    if (t < 64 && h[t]) atomicAdd(&g_dhist[t], h[t]);
}

__global__ void scan2_kernel(int nblocks, int n) {
    int t = threadIdx.x;  // 64 threads
    int v = (t < nblocks) ? g_bsum[t] : 0;
    int x = v;
    int lane = t & 31, wid = t >> 5;
    __shared__ int ws[2];
#pragma unroll
    for (int off = 1; off < 32; off <<= 1) {
        int y = __shfl_up_sync(0xffffffffu, x, off);
        if (lane >= off) x += y;
    }
    if (lane == 31) ws[wid] = x;
    __syncthreads();
    int add = (wid == 1) ? ws[0] : 0;
    g_boff[t] = add + x - v;
    if (t == 63) g_rowptr[n] = add + x;
    if (t == 0) {
        int run = 0;
        for (int i = 0; i < 64; i++) { g_dcur[i] = run; run += g_dhist[i]; }
    }
}

__global__ void scan3_kernel(int n) {
    int idx = blockIdx.x * blockDim.x + threadIdx.x;
    if (idx < n) {
        int r = g_rowptr[idx] + g_boff[idx >> 10];
        g_rowptr[idx] = r;
        g_cursor[idx] = r;
        int pos = atomicAdd(&g_dcur[min(g_deg[idx], 63)], 1);
        g_perm[pos] = idx;
    }
}

__global__ void scatter_kernel(const int* __restrict__ edges, int m) {
    int e = blockIdx.x * blockDim.x + threadIdx.x;
    if (e < m) {
        int d = edges[m + e];
        int pos = atomicAdd(&g_cursor[d], 1);
        g_colsrc[pos] = edges[e];
    }
}

// Sort each row's src list: deterministic accumulation order.
__global__ void sort_rows(int n) {
    int node = blockIdx.x * blockDim.x + threadIdx.x;
    if (node >= n) return;
    int s = g_rowptr[node], e = g_rowptr[node + 1];
    for (int i = s + 1; i < e; i++) {
        int v = g_colsrc[i];
        int j = i - 1;
        while (j >= s && g_colsrc[j] > v) { g_colsrc[j + 1] = g_colsrc[j]; j--; }
        g_colsrc[j + 1] = v;
    }
}

// ---------------------------------------------------------------------------
// half2 views of a 16B+8B smem entry
__device__ __forceinline__ __half2 h2of(unsigned u) { return *(__half2*)&u; }

// dot of one edge (6 half2 words) against c (half2): HFMA2 chain, no cvt
__device__ __forceinline__ float dot12h(uint4 a, uint2 b, const __half2* ch) {
    __half2 d0 = __hmul2(h2of(a.x), ch[0]);
    __half2 d1 = __hmul2(h2of(a.y), ch[1]);
    d0 = __hfma2(h2of(a.z), ch[2], d0);
    d1 = __hfma2(h2of(a.w), ch[3], d1);
    d0 = __hfma2(h2of(b.x), ch[4], d0);
    d1 = __hfma2(h2of(b.y), ch[5], d1);
    float2 t = __half22float2(__hadd2(d0, d1));
    return t.x + t.y;
}

// acc_h[i] += p2 * edge[i]   (6 HFMA2)
__device__ __forceinline__ void acc12h(uint4 a, uint2 b, __half2 p2, __half2* acc_h) {
    acc_h[0] = __hfma2(p2, h2of(a.x), acc_h[0]);
    acc_h[1] = __hfma2(p2, h2of(a.y), acc_h[1]);
    acc_h[2] = __hfma2(p2, h2of(a.z), acc_h[2]);
    acc_h[3] = __hfma2(p2, h2of(a.w), acc_h[3]);
    acc_h[4] = __hfma2(p2, h2of(b.x), acc_h[4]);
    acc_h[5] = __hfma2(p2, h2of(b.y), acc_h[5]);
}

// paired step: dot+softmax+acc for 2 edges, ONE half2 butterfly for both sums
__device__ __forceinline__ void pair_step(uint4 Aa, uint2 Ba, uint4 Ab, uint2 Bb,
                                          const __half2* ch, unsigned mask,
                                          __half2* acc_h) {
    float ex0 = __expf(dot12h(Aa, Ba, ch));
    float ex1 = __expf(dot12h(Ab, Bb, ch));
    __half2 sh = hsum8(__floats2half2_rn(ex0, ex1), mask);
    float2 sf = __half22float2(sh);
    __half2 p0h = __float2half2_rn(__fdividef(ex0, sf.x));
    __half2 p1h = __float2half2_rn(__fdividef(ex1, sf.y));
    acc12h(Aa, Ba, p0h, acc_h);
    acc12h(Ab, Bb, p1h, acc_h);
}

__device__ __forceinline__ void solo_step(uint4 A, uint2 B, const __half2* ch,
                                          unsigned mask, __half2* acc_h) {
    float ex = __expf(dot12h(A, B, ch));
    float sm_ = gsum8(ex, mask);
    __half2 ph = __float2half2_rn(__fdividef(ex, sm_));
    acc12h(A, B, ph, acc_h);
}

// Persistent ALL-LAYERS routing kernel. One wave (592 blocks, 4/SM);
// device-side global barrier between layers; per-WARP work stealing in
// 4-node chunks. half2 inner math; PAIRED softmax butterfly (one 3-step
// half2 butterfly per 2 edges); iteration 0 fused into the fill pass
// (dot/softmax/acc computed from the LDG registers while storing smem);
// iterations 1-5 read smem. Softmax divisions stay fp32.
// Layers 0-2: z_next = l2norm(relu(c)) -> other buffer. Layer 3: relu(c) -> fout.
__global__ void __launch_bounds__(128, 4)
routing_all(__half* __restrict__ zha, float* __restrict__ z32a,
            __half* __restrict__ zhb, float* __restrict__ z32b,
            float* __restrict__ fout, int n) {
    extern __shared__ char sm[];
    int lane = threadIdx.x & 31;
    int warp = threadIdx.x >> 5;
    int group = lane >> 3;
    int cap = lane & 7;
    unsigned mask = 0xFFu << (group << 3);
    int nchunks = (n + 3) / 4;

    char* wslab = sm + warp * WSLAB;

    for (int layer = 0; layer < 4; layer++) {
        const __half* zh_in  = (layer & 1) ? zhb : zha;
        const float* z32_in  = (layer & 1) ? z32b : z32a;
        __half* zh_out       = (layer & 1) ? zha : zhb;
        float* z32_out       = (layer & 1) ? z32a : z32b;
        int last = (layer == 3);

        while (true) {
            int chunk;
            if (lane == 0) chunk = atomicAdd(&g_work[layer], 1);
            chunk = __shfl_sync(0xffffffffu, chunk, 0);
            if (chunk >= nchunks) break;

            int slot = chunk * 4 + group;
            bool valid = slot < n;
            int node = valid ? g_perm[(n - 1) - slot] : 0;   // descending degree

            int s = 0, deg = 0;
            if (valid) { s = g_rowptr[node]; deg = g_rowptr[node + 1] - s; }
            int cached = min(deg, CAP);

            // ---- z_self (fp32); c init = z; ch = half2(c) ----
            float z[12], c[12];
            __half2 ch[6];
            if (valid) {
                const float4* zb = (const float4*)(z32_in + (size_t)node * D + cap * FAC);
                float4 a0 = zb[0], a1 = zb[1], a2 = zb[2];
                z[0] = a0.x; z[1] = a0.y; z[2]  = a0.z; z[3]  = a0.w;
                z[4] = a1.x; z[5] = a1.y; z[6]  = a1.z; z[7]  = a1.w;
                z[8] = a2.x; z[9] = a2.y; z[10] = a2.z; z[11] = a2.w;
            } else {
#pragma unroll
                for (int i = 0; i < 12; i++) z[i] = 0.f;
            }
#pragma unroll
            for (int i = 0; i < 12; i++) c[i] = z[i];
#pragma unroll
            for (int i = 0; i < 6; i++) ch[i] = __floats2half2_rn(c[2 * i], c[2 * i + 1]);

            // ---- fill + ITERATION 0 fused (1-pair-ahead LDG prefetch) ----
            __half2 acc_h[6];
#pragma unroll
            for (int i = 0; i < 6; i++) acc_h[i] = __floats2half2_rn(0.f, 0.f);
            {
                int e = 0;
                uint2 Pa0, Pa1, Pa2, Pb0, Pb1, Pb2;
                if (e + 1 < cached) {
                    const uint2* ga = (const uint2*)(zh_in + (size_t)g_colsrc[s + e] * D) + cap * 3;
                    const uint2* gb = (const uint2*)(zh_in + (size_t)g_colsrc[s + e + 1] * D) + cap * 3;
                    Pa0 = ga[0]; Pa1 = ga[1]; Pa2 = ga[2];
                    Pb0 = gb[0]; Pb1 = gb[1]; Pb2 = gb[2];
                }
                for (; e + 1 < cached; e += 2) {
                    uint2 Qa0 = Pa0, Qa1 = Pa1, Qa2 = Pa2;
                    uint2 Qb0 = Pb0, Qb1 = Pb1, Qb2 = Pb2;
                    if (e + 3 < cached) {
                        const uint2* ga = (const uint2*)(zh_in + (size_t)g_colsrc[s + e + 2] * D) + cap * 3;
                        const uint2* gb = (const uint2*)(zh_in + (size_t)g_colsrc[s + e + 3] * D) + cap * 3;
                        Pa0 = ga[0]; Pa1 = ga[1]; Pa2 = ga[2];
                        Pb0 = gb[0]; Pb1 = gb[1]; Pb2 = gb[2];
                    }
                    char* eb = wslab + e * 768;
                    *(uint4*)(eb + lane * 16) = make_uint4(Qa0.x, Qa0.y, Qa1.x, Qa1.y);
                    *(uint2*)(eb + 512 + lane * 8) = Qa2;
                    eb += 768;
                    *(uint4*)(eb + lane * 16) = make_uint4(Qb0.x, Qb0.y, Qb1.x, Qb1.y);
                    *(uint2*)(eb + 512 + lane * 8) = Qb2;
                    pair_step(make_uint4(Qa0.x, Qa0.y, Qa1.x, Qa1.y), Qa2,
                              make_uint4(Qb0.x, Qb0.y, Qb1.x, Qb1.y), Qb2,
                              ch, mask, acc_h);
                }
                if (e < cached) {
                    const uint2* ga = (const uint2*)(zh_in + (size_t)g_colsrc[s + e] * D) + cap * 3;
                    uint2 d0 = ga[0], d1 = ga[1], d2 = ga[2];
                    char* eb = wslab + e * 768;
                    *(uint4*)(eb + lane * 16) = make_uint4(d0.x, d0.y, d1.x, d1.y);
                    *(uint2*)(eb + 512 + lane * 8) = d2;
                    solo_step(make_uint4(d0.x, d0.y, d1.x, d1.y), d2, ch, mask, acc_h);
                }
                // overflow edges (iteration 0), pairs then tail
                int e2 = cached;
                for (; e2 + 1 < deg; e2 += 2) {
                    const uint2* ga = (const uint2*)(zh_in + (size_t)g_colsrc[s + e2] * D + cap * FAC);
                    const uint2* gb = (const uint2*)(zh_in + (size_t)g_colsrc[s + e2 + 1] * D + cap * FAC);
                    uint2 A0 = ga[0], A1 = ga[1], A2 = ga[2];
                    uint2 B0 = gb[0], B1 = gb[1], B2 = gb[2];
                    pair_step(make_uint4(A0.x, A0.y, A1.x, A1.y), A2,
                              make_uint4(B0.x, B0.y, B1.x, B1.y), B2,
                              ch, mask, acc_h);
                }
                if (e2 < deg) {
                    const uint2* ga = (const uint2*)(zh_in + (size_t)g_colsrc[s + e2] * D + cap * FAC);
                    uint2 A0 = ga[0], A1 = ga[1], A2 = ga[2];
                    solo_step(make_uint4(A0.x, A0.y, A1.x, A1.y), A2, ch, mask, acc_h);
                }
            }
            // iteration-0 update: c = l2norm(z + acc)
            {
                float v[12];
                float ss = 0.f;
#pragma unroll
                for (int i = 0; i < 6; i++) {
                    float2 h = __half22float2(acc_h[i]);
                    v[2 * i]     = z[2 * i] + h.x;
                    v[2 * i + 1] = z[2 * i + 1] + h.y;
                    ss += v[2 * i] * v[2 * i] + v[2 * i + 1] * v[2 * i + 1];
                }
                float rn = rsqrtf(ss + 1e-12f);
#pragma unroll
                for (int i = 0; i < 12; i++) c[i] = v[i] * rn;
#pragma unroll
                for (int i = 0; i < 6; i++) ch[i] = __floats2half2_rn(c[2 * i], c[2 * i + 1]);
            }

            // ---- iterations 1..5 from smem ----
            for (int it = 1; it < 6; it++) {
#pragma unroll
                for (int i = 0; i < 6; i++) acc_h[i] = __floats2half2_rn(0.f, 0.f);

                int e = 0;
                // 4-edge unrolled (two paired steps)
                for (; e + 3 < cached; e += 4) {
                    const char* p0 = wslab + e * 768;
                    uint4 A0 = *(const uint4*)(p0 + lane * 16);
                    uint2 B0 = *(const uint2*)(p0 + 512 + lane * 8);
                    uint4 A1 = *(const uint4*)(p0 + 768 + lane * 16);
                    uint2 B1 = *(const uint2*)(p0 + 768 + 512 + lane * 8);
                    uint4 A2 = *(const uint4*)(p0 + 1536 + lane * 16);
                    uint2 B2 = *(const uint2*)(p0 + 1536 + 512 + lane * 8);
                    uint4 A3 = *(const uint4*)(p0 + 2304 + lane * 16);
                    uint2 B3 = *(const uint2*)(p0 + 2304 + 512 + lane * 8);
                    pair_step(A0, B0, A1, B1, ch, mask, acc_h);
                    pair_step(A2, B2, A3, B3, ch, mask, acc_h);
                }
                if (e + 1 < cached) {
                    const char* p0 = wslab + e * 768;
                    uint4 A0 = *(const uint4*)(p0 + lane * 16);
                    uint2 B0 = *(const uint2*)(p0 + 512 + lane * 8);
                    uint4 A1 = *(const uint4*)(p0 + 768 + lane * 16);
                    uint2 B1 = *(const uint2*)(p0 + 768 + 512 + lane * 8);
                    pair_step(A0, B0, A1, B1, ch, mask, acc_h);
                    e += 2;
                }
                if (e < cached) {
                    const char* p0 = wslab + e * 768;
                    uint4 A0 = *(const uint4*)(p0 + lane * 16);
                    uint2 B0 = *(const uint2*)(p0 + 512 + lane * 8);
                    solo_step(A0, B0, ch, mask, acc_h);
                }
                // overflow edges from L2, pairs then tail
                int e2 = cached;
                for (; e2 + 1 < deg; e2 += 2) {
                    const uint2* ga = (const uint2*)(zh_in + (size_t)g_colsrc[s + e2] * D + cap * FAC);
                    const uint2* gb = (const uint2*)(zh_in + (size_t)g_colsrc[s + e2 + 1] * D + cap * FAC);
                    uint2 A0 = ga[0], A1 = ga[1], A2 = ga[2];
                    uint2 B0 = gb[0], B1 = gb[1], B2 = gb[2];
                    pair_step(make_uint4(A0.x, A0.y, A1.x, A1.y), A2,
                              make_uint4(B0.x, B0.y, B1.x, B1.y), B2,
                              ch, mask, acc_h);
                }
                if (e2 < deg) {
                    const uint2* ga = (const uint2*)(zh_in + (size_t)g_colsrc[s + e2] * D + cap * FAC);
                    uint2 A0 = ga[0], A1 = ga[1], A2 = ga[2];
                    solo_step(make_uint4(A0.x, A0.y, A1.x, A1.y), A2, ch, mask, acc_h);
                }

                float v[12];
                float ss = 0.f;
#pragma unroll
                for (int i = 0; i < 6; i++) {
                    float2 h = __half22float2(acc_h[i]);
                    v[2 * i]     = z[2 * i] + h.x;
                    v[2 * i + 1] = z[2 * i + 1] + h.y;
                    ss += v[2 * i] * v[2 * i] + v[2 * i + 1] * v[2 * i + 1];
                }
                float rn = rsqrtf(ss + 1e-12f);
#pragma unroll
                for (int i = 0; i < 12; i++) c[i] = v[i] * rn;
#pragma unroll
                for (int i = 0; i < 6; i++) ch[i] = __floats2half2_rn(c[2 * i], c[2 * i + 1]);
            }

            if (valid) {
#pragma unroll
                for (int i = 0; i < 12; i++) c[i] = fmaxf(c[i], 0.f);  // relu
                if (!last) {
                    float ss = 0.f;
#pragma unroll
                    for (int i = 0; i < 12; i++) ss += c[i] * c[i];
                    float rn = rsqrtf(ss + 1e-12f);
#pragma unroll
                    for (int i = 0; i < 12; i++) c[i] *= rn;
                    float4* zp = (float4*)(z32_out + (size_t)node * D + cap * FAC);
                    zp[0] = make_float4(c[0], c[1], c[2], c[3]);
                    zp[1] = make_float4(c[4], c[5], c[6], c[7]);
                    zp[2] = make_float4(c[8], c[9], c[10], c[11]);
                    uint2* zh = (uint2*)(zh_out + (size_t)node * D + cap * FAC);
                    __half2 h0 = __floats2half2_rn(c[0], c[1]);
                    __half2 h1 = __floats2half2_rn(c[2], c[3]);
                    __half2 h2 = __floats2half2_rn(c[4], c[5]);
                    __half2 h3 = __floats2half2_rn(c[6], c[7]);
                    __half2 h4 = __floats2half2_rn(c[8], c[9]);
                    __half2 h5 = __floats2half2_rn(c[10], c[11]);
                    zh[0] = make_uint2(*(unsigned*)&h0, *(unsigned*)&h1);
                    zh[1] = make_uint2(*(unsigned*)&h2, *(unsigned*)&h3);
                    zh[2] = make_uint2(*(unsigned*)&h4, *(unsigned*)&h5);
                } else {
                    float4* fo = (float4*)(fout + (size_t)node * D + cap * FAC);
                    fo[0] = make_float4(c[0], c[1], c[2], c[3]);
                    fo[1] = make_float4(c[4], c[5], c[6], c[7]);
                    fo[2] = make_float4(c[8], c[9], c[10], c[11]);
                }
            }
        }

        if (layer < 3) {
            // global barrier: release writes, arrive, spin until all arrive
            __syncthreads();
            if (threadIdx.x == 0) {
                __threadfence();
                atomicAdd(&g_bar[layer], 1);
                while (((volatile int*)g_bar)[layer] < gridDim.x) { }
            }
            __syncthreads();
            __threadfence();
        }
    }
}

// ---------------------------------------------------------------------------
extern "C" void kernel_launch(void* const* d_in, const int* in_sizes, int n_in,
                              void* d_out, int out_size) {
    const float* X     = (const float*)d_in[0];
    const int*   edges = (const int*)d_in[1];
    const float* W     = (const float*)d_in[2];
    const float* b     = (const float*)d_in[3];
    int n = in_sizes[0] / 256;   // 50000
    int m = in_sizes[1] / 2;     // 800000

    cudaFuncSetAttribute(routing_all,
                         cudaFuncAttributeMaxDynamicSharedMemorySize, ROUTE_SMEM);

    __half* zha; cudaGetSymbolAddress((void**)&zha, g_zh_a);
    __half* zhb; cudaGetSymbolAddress((void**)&zhb, g_zh_b);
    float* z32a; cudaGetSymbolAddress((void**)&z32a, g_z32_a);
    float* z32b; cudaGetSymbolAddress((void**)&z32b, g_z32_b);

    // zero + W transpose + counter reset, then init+prep fused
    zero_wt_kernel<<<(n + 255) / 256, 256>>>(W, n);
    init_gemm<<<(n + 31) / 32, 96>>>(X, b, n);

    // CSR by dst (deterministic: rows sorted by src); perm fused into scans
    hist_kernel<<<(m + 255) / 256, 256>>>(edges, m);
    int sblocks = (n + 1023) / 1024;   // 49 <= 64
    scan1_kernel<<<sblocks, 1024>>>(n);
    scan2_kernel<<<1, 64>>>(sblocks, n);
    scan3_kernel<<<(n + 255) / 256, 256>>>(n);
    scatter_kernel<<<(m + 255) / 256, 256>>>(edges, m);
    sort_rows<<<(n + 255) / 256, 256>>>(n);

    // single persistent kernel: all 4 routing layers with device barriers
    routing_all<<<ROUTE_GRID, 128, ROUTE_SMEM>>>(zha, z32a, zhb, z32b,
                                                 (float*)d_out, n);
}

// round 17
// speedup vs baseline: 1.1839x; 1.0260x over previous
#include <cuda_runtime.h>
#include <cuda_fp16.h>

// Problem constants (fixed shapes)
#define N_MAX 50000
#define M_MAX 800000
#define D 96          // K*FAC
#define KCAP 8
#define FAC 12
#define LOG2E 1.44269504f

#define CAP 18                        // cached neighbors per node in smem (fp16)
#define WSLAB (CAP * 768)             // per-warp slab: CAP entries x 768B
#define ROUTE_SMEM (4 * WSLAB)        // 55296 B per 128-thread block -> 4 blocks/SM
#define ROUTE_GRID 592                // 148 SMs x 4 resident blocks: exactly one wave

typedef unsigned long long u64;

// Static scratch (no allocations allowed)
__device__ __half g_zh_a[N_MAX * D];   // fp16 z double-buffer A (gather source)
__device__ __half g_zh_b[N_MAX * D];   // fp16 z double-buffer B
__device__ float  g_z32_a[N_MAX * D];  // fp32 z double-buffer A (self-term)
__device__ float  g_z32_b[N_MAX * D];  // fp32 z double-buffer B
__device__ float  g_wt[D * 256];       // W transposed to [out=96][in=256]
__device__ int    g_deg[N_MAX];
__device__ int    g_rowptr[N_MAX + 1];
__device__ int    g_cursor[N_MAX];
__device__ int    g_colsrc[M_MAX];
__device__ int    g_bsum[64];
__device__ int    g_boff[64];
__device__ int    g_dhist[64];
__device__ int    g_dcur[64];
__device__ int    g_perm[N_MAX];
__device__ int    g_work[4];           // per-layer work-stealing counters
__device__ int    g_bar[4];            // per-layer global barrier counters

// ---------------- packed f32x2 helpers (init GEMM only) --------------------
__device__ __forceinline__ u64 pk2(float lo, float hi) {
    u64 r; asm("mov.b64 %0,{%1,%2};" : "=l"(r) : "f"(lo), "f"(hi)); return r;
}
__device__ __forceinline__ float2 upk2(u64 v) {
    float2 f; asm("mov.b64 {%0,%1},%2;" : "=f"(f.x), "=f"(f.y) : "l"(v)); return f;
}
__device__ __forceinline__ u64 fma2_(u64 a, u64 b, u64 c) {
    u64 d; asm("fma.rn.f32x2 %0,%1,%2,%3;" : "=l"(d) : "l"(a), "l"(b), "l"(c)); return d;
}

// 8-lane group sum, fp32 (solo-edge path)
__device__ __forceinline__ float gsum8(float v, unsigned mask) {
    v += __shfl_xor_sync(mask, v, 1);
    v += __shfl_xor_sync(mask, v, 2);
    v += __shfl_xor_sync(mask, v, 4);
    return v;
}

// 8-lane group sum of an (ex0, ex1) pair packed in half2: one butterfly for 2 edges
__device__ __forceinline__ __half2 hsum8(__half2 v, unsigned mask) {
    unsigned u = *(unsigned*)&v, r;
    r = __shfl_xor_sync(mask, u, 1); v = __hadd2(v, *(__half2*)&r); u = *(unsigned*)&v;
    r = __shfl_xor_sync(mask, u, 2); v = __hadd2(v, *(__half2*)&r); u = *(unsigned*)&v;
    r = __shfl_xor_sync(mask, u, 4); v = __hadd2(v, *(__half2*)&r);
    return v;
}

// ---------------------------------------------------------------------------
// zero + W transpose fused; also resets work/barrier counters each replay.
__global__ void zero_wt_kernel(const float* __restrict__ W, int n) {
    int i = blockIdx.x * blockDim.x + threadIdx.x;
    if (i < n) g_deg[i] = 0;
    if (i < 64) g_dhist[i] = 0;
    if (i < 4) { g_work[i] = 0; g_bar[i] = 0; }
    if (i < D * 256) {
        int o = i >> 8, c = i & 255;
        int k = o / FAC, oo = o % FAC;
        g_wt[i] = W[k * (256 * FAC) + c * FAC + oo];
    }
}

// ---------------------------------------------------------------------------
// Init layer fused with prep: Z = relu(X.Wt + b) staged in smem, then
// z = l2norm(Z) written to z32_a (fp32) + zh_a (fp16). f32x2 FMA mainloop.
__global__ void __launch_bounds__(96) init_gemm(const float* __restrict__ X,
                                                const float* __restrict__ bv, int n) {
    __shared__ float xs[32][256];
    __shared__ float os[32][96];
    int t = threadIdx.x;
    int nb = blockIdx.x * 32;
    for (int j = t; j < 32 * 256; j += 96) {
        int q = j >> 8;
        xs[q][j & 255] = (nb + q < n) ? X[nb * 256 + j] : 0.f;
    }
    __syncthreads();

    u64 acc[32];
#pragma unroll
    for (int q = 0; q < 32; q++) acc[q] = 0ull;

    const float4* wrow = (const float4*)(g_wt + t * 256);
#pragma unroll 2
    for (int i4 = 0; i4 < 64; i4++) {
        float4 w = wrow[i4];
        u64 w01 = pk2(w.x, w.y);
        u64 w23 = pk2(w.z, w.w);
#pragma unroll
        for (int q = 0; q < 32; q++) {
            float4 xv = *(const float4*)&xs[q][i4 * 4];
            acc[q] = fma2_(w01, pk2(xv.x, xv.y), acc[q]);
            acc[q] = fma2_(w23, pk2(xv.z, xv.w), acc[q]);
        }
    }
    float bb = bv[t];
#pragma unroll
    for (int q = 0; q < 32; q++) {
        float2 h = upk2(acc[q]);
        os[q][t] = fmaxf(h.x + h.y + bb, 0.f);   // relu(Z)
    }
    __syncthreads();

    // prep: per (node, capsule) l2norm -> z32_a + zh_a (fp16)
    for (int idx = t; idx < 32 * KCAP; idx += 96) {
        int q = idx >> 3, cp = idx & 7;
        if (nb + q >= n) continue;
        const float* r = &os[q][cp * FAC];
        float v[12];
        float s = 0.f;
#pragma unroll
        for (int i = 0; i < 12; i++) { v[i] = r[i]; s += v[i] * v[i]; }
        float rn = rsqrtf(s + 1e-12f);
#pragma unroll
        for (int i = 0; i < 12; i++) v[i] *= rn;
        int gi = ((nb + q) * KCAP + cp) * FAC;
        float4* zp = (float4*)(g_z32_a + gi);
        zp[0] = make_float4(v[0], v[1], v[2], v[3]);
        zp[1] = make_float4(v[4], v[5], v[6], v[7]);
        zp[2] = make_float4(v[8], v[9], v[10], v[11]);
        uint2* zh = (uint2*)(g_zh_a + gi);
        __half2 h0 = __floats2half2_rn(v[0], v[1]);
        __half2 h1 = __floats2half2_rn(v[2], v[3]);
        __half2 h2 = __floats2half2_rn(v[4], v[5]);
        __half2 h3 = __floats2half2_rn(v[6], v[7]);
        __half2 h4 = __floats2half2_rn(v[8], v[9]);
        __half2 h5 = __floats2half2_rn(v[10], v[11]);
        zh[0] = make_uint2(*(unsigned*)&h0, *(unsigned*)&h1);
        zh[1] = make_uint2(*(unsigned*)&h2, *(unsigned*)&h3);
        zh[2] = make_uint2(*(unsigned*)&h4, *(unsigned*)&h5);
    }
}

// ---------------------------------------------------------------------------
// CSR build: hist -> 3-phase hierarchical scan (with perm stages fused)
__global__ void hist_kernel(const int* __restrict__ edges, int m) {
    int e = blockIdx.x * blockDim.x + threadIdx.x;
    if (e < m) atomicAdd(&g_deg[edges[m + e]], 1);
}

__global__ void scan1_kernel(int n) {
    __shared__ int wsum[32];
    __shared__ int h[64];
    int t = threadIdx.x, lane = t & 31, wid = t >> 5;
    if (t < 64) h[t] = 0;
    int idx = blockIdx.x * 1024 + t;
    int v = (idx < n) ? g_deg[idx] : 0;
    int x = v;
#pragma unroll
    for (int off = 1; off < 32; off <<= 1) {
        int y = __shfl_up_sync(0xffffffffu, x, off);
        if (lane >= off) x += y;
    }
    if (lane == 31) wsum[wid] = x;
    __syncthreads();
    if (wid == 0) {
        int w = wsum[lane];
#pragma unroll
        for (int off = 1; off < 32; off <<= 1) {
            int y = __shfl_up_sync(0xffffffffu, w, off);
            if (lane >= off) w += y;
        }
        wsum[lane] = w;
    }
    if (idx < n) atomicAdd(&h[min(v, 63)], 1);
    __syncthreads();
    int pre = (wid > 0) ? wsum[wid - 1] : 0;
    if (idx < n) g_rowptr[idx] = pre + x - v;   // block-local exclusive
    if (t == 1023) g_bsum[blockIdx.x] = pre + x;
    if (t < 64 && h[t]) atomicAdd(&g_dhist[t], h[t]);
}

__global__ void scan2_kernel(int nblocks, int n) {
    int t = threadIdx.x;  // 64 threads
    int v = (t < nblocks) ? g_bsum[t] : 0;
    int x = v;
    int lane = t & 31, wid = t >> 5;
    __shared__ int ws[2];
#pragma unroll
    for (int off = 1; off < 32; off <<= 1) {
        int y = __shfl_up_sync(0xffffffffu, x, off);
        if (lane >= off) x += y;
    }
    if (lane == 31) ws[wid] = x;
    __syncthreads();
    int add = (wid == 1) ? ws[0] : 0;
    g_boff[t] = add + x - v;
    if (t == 63) g_rowptr[n] = add + x;
    if (t == 0) {
        int run = 0;
        for (int i = 0; i < 64; i++) { g_dcur[i] = run; run += g_dhist[i]; }
    }
}

__global__ void scan3_kernel(int n) {
    int idx = blockIdx.x * blockDim.x + threadIdx.x;
    if (idx < n) {
        int r = g_rowptr[idx] + g_boff[idx >> 10];
        g_rowptr[idx] = r;
        g_cursor[idx] = r;
        int pos = atomicAdd(&g_dcur[min(g_deg[idx], 63)], 1);
        g_perm[pos] = idx;
    }
}

__global__ void scatter_kernel(const int* __restrict__ edges, int m) {
    int e = blockIdx.x * blockDim.x + threadIdx.x;
    if (e < m) {
        int d = edges[m + e];
        int pos = atomicAdd(&g_cursor[d], 1);
        g_colsrc[pos] = edges[e];
    }
}

// Sort each row's src list: deterministic accumulation order.
__global__ void sort_rows(int n) {
    int node = blockIdx.x * blockDim.x + threadIdx.x;
    if (node >= n) return;
    int s = g_rowptr[node], e = g_rowptr[node + 1];
    for (int i = s + 1; i < e; i++) {
        int v = g_colsrc[i];
        int j = i - 1;
        while (j >= s && g_colsrc[j] > v) { g_colsrc[j + 1] = g_colsrc[j]; j--; }
        g_colsrc[j + 1] = v;
    }
}

// ---------------------------------------------------------------------------
// half2 views of a 16B+8B smem entry
__device__ __forceinline__ __half2 h2of(unsigned u) { return *(__half2*)&u; }

// dot of one edge against ch (c pre-scaled by log2e): result att*log2e as half
__device__ __forceinline__ __half dot12hh(uint4 a, uint2 b, const __half2* ch) {
    __half2 d0 = __hmul2(h2of(a.x), ch[0]);
    __half2 d1 = __hmul2(h2of(a.y), ch[1]);
    d0 = __hfma2(h2of(a.z), ch[2], d0);
    d1 = __hfma2(h2of(a.w), ch[3], d1);
    d0 = __hfma2(h2of(b.x), ch[4], d0);
    d1 = __hfma2(h2of(b.y), ch[5], d1);
    __half2 d = __hadd2(d0, d1);
    d = __hadd2(d, __lowhigh2highlow(d));   // horizontal add, att in both halves
    return __low2half(d);
}

// acc_h[i] += p2 * edge[i]   (6 HFMA2)
__device__ __forceinline__ void acc12h(uint4 a, uint2 b, __half2 p2, __half2* acc_h) {
    acc_h[0] = __hfma2(p2, h2of(a.x), acc_h[0]);
    acc_h[1] = __hfma2(p2, h2of(a.y), acc_h[1]);
    acc_h[2] = __hfma2(p2, h2of(a.z), acc_h[2]);
    acc_h[3] = __hfma2(p2, h2of(a.w), acc_h[3]);
    acc_h[4] = __hfma2(p2, h2of(b.x), acc_h[4]);
    acc_h[5] = __hfma2(p2, h2of(b.y), acc_h[5]);
}

// paired step, full f16x2 softmax path: one h2exp2 + one butterfly + one h2rcp
// handles BOTH edges (ch is pre-scaled by log2e so exp == exp2).
__device__ __forceinline__ void pair_step(uint4 Aa, uint2 Ba, uint4 Ab, uint2 Bb,
                                          const __half2* ch, unsigned mask,
                                          __half2* acc_h) {
    __half2 attp = __halves2half2(dot12hh(Aa, Ba, ch), dot12hh(Ab, Bb, ch));
    __half2 exp_ = h2exp2(attp);           // (exA, exB), one MUFU
    __half2 sh = hsum8(exp_, mask);        // (sA, sB)
    __half2 pp = __hmul2(exp_, h2rcp(sh)); // (pA, pB)
    acc12h(Aa, Ba, __half2half2(__low2half(pp)), acc_h);
    acc12h(Ab, Bb, __half2half2(__high2half(pp)), acc_h);
}

__device__ __forceinline__ void solo_step(uint4 A, uint2 B, const __half2* ch,
                                          unsigned mask, __half2* acc_h) {
    float ex = exp2f(__half2float(dot12hh(A, B, ch)));
    float sm_ = gsum8(ex, mask);
    __half2 ph = __float2half2_rn(__fdividef(ex, sm_));
    acc12h(A, B, ph, acc_h);
}

// pack c into half2 pre-scaled by log2e (dot then feeds exp2 directly)
__device__ __forceinline__ void makech(const float* c, __half2* ch) {
#pragma unroll
    for (int i = 0; i < 6; i++)
        ch[i] = __floats2half2_rn(c[2 * i] * LOG2E, c[2 * i + 1] * LOG2E);
}

// Persistent ALL-LAYERS routing kernel. One wave (592 blocks, 4/SM);
// device-side global barrier between layers; per-WARP work stealing in
// 4-node chunks. Full f16x2 inner path: HFMA2 dot (c pre-scaled by log2e),
// h2exp2 + paired half2 butterfly + h2rcp softmax, HFMA2 accumulate.
// Iteration 0 fused into the fill pass; iterations 1-5 read smem.
// Layers 0-2: z_next = l2norm(relu(c)) -> other buffer. Layer 3: relu(c) -> fout.
__global__ void __launch_bounds__(128, 4)
routing_all(__half* __restrict__ zha, float* __restrict__ z32a,
            __half* __restrict__ zhb, float* __restrict__ z32b,
            float* __restrict__ fout, int n) {
    extern __shared__ char sm[];
    int lane = threadIdx.x & 31;
    int warp = threadIdx.x >> 5;
    int group = lane >> 3;
    int cap = lane & 7;
    unsigned mask = 0xFFu << (group << 3);
    int nchunks = (n + 3) / 4;

    char* wslab = sm + warp * WSLAB;

    for (int layer = 0; layer < 4; layer++) {
        const __half* zh_in  = (layer & 1) ? zhb : zha;
        const float* z32_in  = (layer & 1) ? z32b : z32a;
        __half* zh_out       = (layer & 1) ? zha : zhb;
        float* z32_out       = (layer & 1) ? z32a : z32b;
        int last = (layer == 3);

        while (true) {
            int chunk;
            if (lane == 0) chunk = atomicAdd(&g_work[layer], 1);
            chunk = __shfl_sync(0xffffffffu, chunk, 0);
            if (chunk >= nchunks) break;

            int slot = chunk * 4 + group;
            bool valid = slot < n;
            int node = valid ? g_perm[(n - 1) - slot] : 0;   // descending degree

            int s = 0, deg = 0;
            if (valid) { s = g_rowptr[node]; deg = g_rowptr[node + 1] - s; }
            int cached = min(deg, CAP);

            // ---- z_self (fp32); c init = z; ch = half2(c * log2e) ----
            float z[12], c[12];
            __half2 ch[6];
            if (valid) {
                const float4* zb = (const float4*)(z32_in + (size_t)node * D + cap * FAC);
                float4 a0 = zb[0], a1 = zb[1], a2 = zb[2];
                z[0] = a0.x; z[1] = a0.y; z[2]  = a0.z; z[3]  = a0.w;
                z[4] = a1.x; z[5] = a1.y; z[6]  = a1.z; z[7]  = a1.w;
                z[8] = a2.x; z[9] = a2.y; z[10] = a2.z; z[11] = a2.w;
            } else {
#pragma unroll
                for (int i = 0; i < 12; i++) z[i] = 0.f;
            }
#pragma unroll
            for (int i = 0; i < 12; i++) c[i] = z[i];
            makech(c, ch);

            // ---- fill + ITERATION 0 fused (1-pair-ahead LDG prefetch) ----
            __half2 acc_h[6];
#pragma unroll
            for (int i = 0; i < 6; i++) acc_h[i] = __floats2half2_rn(0.f, 0.f);
            {
                int e = 0;
                uint2 Pa0, Pa1, Pa2, Pb0, Pb1, Pb2;
                if (e + 1 < cached) {
                    const uint2* ga = (const uint2*)(zh_in + (size_t)g_colsrc[s + e] * D) + cap * 3;
                    const uint2* gb = (const uint2*)(zh_in + (size_t)g_colsrc[s + e + 1] * D) + cap * 3;
                    Pa0 = ga[0]; Pa1 = ga[1]; Pa2 = ga[2];
                    Pb0 = gb[0]; Pb1 = gb[1]; Pb2 = gb[2];
                }
                for (; e + 1 < cached; e += 2) {
                    uint2 Qa0 = Pa0, Qa1 = Pa1, Qa2 = Pa2;
                    uint2 Qb0 = Pb0, Qb1 = Pb1, Qb2 = Pb2;
                    if (e + 3 < cached) {
                        const uint2* ga = (const uint2*)(zh_in + (size_t)g_colsrc[s + e + 2] * D) + cap * 3;
                        const uint2* gb = (const uint2*)(zh_in + (size_t)g_colsrc[s + e + 3] * D) + cap * 3;
                        Pa0 = ga[0]; Pa1 = ga[1]; Pa2 = ga[2];
                        Pb0 = gb[0]; Pb1 = gb[1]; Pb2 = gb[2];
                    }
                    char* eb = wslab + e * 768;
                    *(uint4*)(eb + lane * 16) = make_uint4(Qa0.x, Qa0.y, Qa1.x, Qa1.y);
                    *(uint2*)(eb + 512 + lane * 8) = Qa2;
                    eb += 768;
                    *(uint4*)(eb + lane * 16) = make_uint4(Qb0.x, Qb0.y, Qb1.x, Qb1.y);
                    *(uint2*)(eb + 512 + lane * 8) = Qb2;
                    pair_step(make_uint4(Qa0.x, Qa0.y, Qa1.x, Qa1.y), Qa2,
                              make_uint4(Qb0.x, Qb0.y, Qb1.x, Qb1.y), Qb2,
                              ch, mask, acc_h);
                }
                if (e < cached) {
                    const uint2* ga = (const uint2*)(zh_in + (size_t)g_colsrc[s + e] * D) + cap * 3;
                    uint2 d0 = ga[0], d1 = ga[1], d2 = ga[2];
                    char* eb = wslab + e * 768;
                    *(uint4*)(eb + lane * 16) = make_uint4(d0.x, d0.y, d1.x, d1.y);
                    *(uint2*)(eb + 512 + lane * 8) = d2;
                    solo_step(make_uint4(d0.x, d0.y, d1.x, d1.y), d2, ch, mask, acc_h);
                }
                // overflow edges (iteration 0), pairs then tail
                int e2 = cached;
                for (; e2 + 1 < deg; e2 += 2) {
                    const uint2* ga = (const uint2*)(zh_in + (size_t)g_colsrc[s + e2] * D + cap * FAC);
                    const uint2* gb = (const uint2*)(zh_in + (size_t)g_colsrc[s + e2 + 1] * D + cap * FAC);
                    uint2 A0 = ga[0], A1 = ga[1], A2 = ga[2];
                    uint2 B0 = gb[0], B1 = gb[1], B2 = gb[2];
                    pair_step(make_uint4(A0.x, A0.y, A1.x, A1.y), A2,
                              make_uint4(B0.x, B0.y, B1.x, B1.y), B2,
                              ch, mask, acc_h);
                }
                if (e2 < deg) {
                    const uint2* ga = (const uint2*)(zh_in + (size_t)g_colsrc[s + e2] * D + cap * FAC);
                    uint2 A0 = ga[0], A1 = ga[1], A2 = ga[2];
                    solo_step(make_uint4(A0.x, A0.y, A1.x, A1.y), A2, ch, mask, acc_h);
                }
            }
            // iteration-0 update: c = l2norm(z + acc)
            {
                float v[12];
                float ss = 0.f;
#pragma unroll
                for (int i = 0; i < 6; i++) {
                    float2 h = __half22float2(acc_h[i]);
                    v[2 * i]     = z[2 * i] + h.x;
                    v[2 * i + 1] = z[2 * i + 1] + h.y;
                    ss += v[2 * i] * v[2 * i] + v[2 * i + 1] * v[2 * i + 1];
                }
                float rn = rsqrtf(ss + 1e-12f);
#pragma unroll
                for (int i = 0; i < 12; i++) c[i] = v[i] * rn;
                makech(c, ch);
            }

            // ---- iterations 1..5 from smem ----
            for (int it = 1; it < 6; it++) {
#pragma unroll
                for (int i = 0; i < 6; i++) acc_h[i] = __floats2half2_rn(0.f, 0.f);

                int e = 0;
                // 4-edge unrolled (two paired steps)
                for (; e + 3 < cached; e += 4) {
                    const char* p0 = wslab + e * 768;
                    uint4 A0 = *(const uint4*)(p0 + lane * 16);
                    uint2 B0 = *(const uint2*)(p0 + 512 + lane * 8);
                    uint4 A1 = *(const uint4*)(p0 + 768 + lane * 16);
                    uint2 B1 = *(const uint2*)(p0 + 768 + 512 + lane * 8);
                    uint4 A2 = *(const uint4*)(p0 + 1536 + lane * 16);
                    uint2 B2 = *(const uint2*)(p0 + 1536 + 512 + lane * 8);
                    uint4 A3 = *(const uint4*)(p0 + 2304 + lane * 16);
                    uint2 B3 = *(const uint2*)(p0 + 2304 + 512 + lane * 8);
                    pair_step(A0, B0, A1, B1, ch, mask, acc_h);
                    pair_step(A2, B2, A3, B3, ch, mask, acc_h);
                }
                if (e + 1 < cached) {
                    const char* p0 = wslab + e * 768;
                    uint4 A0 = *(const uint4*)(p0 + lane * 16);
                    uint2 B0 = *(const uint2*)(p0 + 512 + lane * 8);
                    uint4 A1 = *(const uint4*)(p0 + 768 + lane * 16);
                    uint2 B1 = *(const uint2*)(p0 + 768 + 512 + lane * 8);
                    pair_step(A0, B0, A1, B1, ch, mask, acc_h);
                    e += 2;
                }
                if (e < cached) {
                    const char* p0 = wslab + e * 768;
                    uint4 A0 = *(const uint4*)(p0 + lane * 16);
                    uint2 B0 = *(const uint2*)(p0 + 512 + lane * 8);
                    solo_step(A0, B0, ch, mask, acc_h);
                }
                // overflow edges from L2, pairs then tail
                int e2 = cached;
                for (; e2 + 1 < deg; e2 += 2) {
                    const uint2* ga = (const uint2*)(zh_in + (size_t)g_colsrc[s + e2] * D + cap * FAC);
                    const uint2* gb = (const uint2*)(zh_in + (size_t)g_colsrc[s + e2 + 1] * D + cap * FAC);
                    uint2 A0 = ga[0], A1 = ga[1], A2 = ga[2];
                    uint2 B0 = gb[0], B1 = gb[1], B2 = gb[2];
                    pair_step(make_uint4(A0.x, A0.y, A1.x, A1.y), A2,
                              make_uint4(B0.x, B0.y, B1.x, B1.y), B2,
                              ch, mask, acc_h);
                }
                if (e2 < deg) {
                    const uint2* ga = (const uint2*)(zh_in + (size_t)g_colsrc[s + e2] * D + cap * FAC);
                    uint2 A0 = ga[0], A1 = ga[1], A2 = ga[2];
                    solo_step(make_uint4(A0.x, A0.y, A1.x, A1.y), A2, ch, mask, acc_h);
                }

                float v[12];
                float ss = 0.f;
#pragma unroll
                for (int i = 0; i < 6; i++) {
                    float2 h = __half22float2(acc_h[i]);
                    v[2 * i]     = z[2 * i] + h.x;
                    v[2 * i + 1] = z[2 * i + 1] + h.y;
                    ss += v[2 * i] * v[2 * i] + v[2 * i + 1] * v[2 * i + 1];
                }
                float rn = rsqrtf(ss + 1e-12f);
#pragma unroll
                for (int i = 0; i < 12; i++) c[i] = v[i] * rn;
                makech(c, ch);
            }

            if (valid) {
#pragma unroll
                for (int i = 0; i < 12; i++) c[i] = fmaxf(c[i], 0.f);  // relu
                if (!last) {
                    float ss = 0.f;
#pragma unroll
                    for (int i = 0; i < 12; i++) ss += c[i] * c[i];
                    float rn = rsqrtf(ss + 1e-12f);
#pragma unroll
                    for (int i = 0; i < 12; i++) c[i] *= rn;
                    float4* zp = (float4*)(z32_out + (size_t)node * D + cap * FAC);
                    zp[0] = make_float4(c[0], c[1], c[2], c[3]);
                    zp[1] = make_float4(c[4], c[5], c[6], c[7]);
                    zp[2] = make_float4(c[8], c[9], c[10], c[11]);
                    uint2* zh = (uint2*)(zh_out + (size_t)node * D + cap * FAC);
                    __half2 h0 = __floats2half2_rn(c[0], c[1]);
                    __half2 h1 = __floats2half2_rn(c[2], c[3]);
                    __half2 h2 = __floats2half2_rn(c[4], c[5]);
                    __half2 h3 = __floats2half2_rn(c[6], c[7]);
                    __half2 h4 = __floats2half2_rn(c[8], c[9]);
                    __half2 h5 = __floats2half2_rn(c[10], c[11]);
                    zh[0] = make_uint2(*(unsigned*)&h0, *(unsigned*)&h1);
                    zh[1] = make_uint2(*(unsigned*)&h2, *(unsigned*)&h3);
                    zh[2] = make_uint2(*(unsigned*)&h4, *(unsigned*)&h5);
                } else {
                    float4* fo = (float4*)(fout + (size_t)node * D + cap * FAC);
                    fo[0] = make_float4(c[0], c[1], c[2], c[3]);
                    fo[1] = make_float4(c[4], c[5], c[6], c[7]);
                    fo[2] = make_float4(c[8], c[9], c[10], c[11]);
                }
            }
        }

        if (layer < 3) {
            // global barrier: release writes, arrive, spin until all arrive
            __syncthreads();
            if (threadIdx.x == 0) {
                __threadfence();
                atomicAdd(&g_bar[layer], 1);
                while (((volatile int*)g_bar)[layer] < gridDim.x) { }
            }
            __syncthreads();
            __threadfence();
        }
    }
}

// ---------------------------------------------------------------------------
extern "C" void kernel_launch(void* const* d_in, const int* in_sizes, int n_in,
                              void* d_out, int out_size) {
    const float* X     = (const float*)d_in[0];
    const int*   edges = (const int*)d_in[1];
    const float* W     = (const float*)d_in[2];
    const float* b     = (const float*)d_in[3];
    int n = in_sizes[0] / 256;   // 50000
    int m = in_sizes[1] / 2;     // 800000

    cudaFuncSetAttribute(routing_all,
                         cudaFuncAttributeMaxDynamicSharedMemorySize, ROUTE_SMEM);

    __half* zha; cudaGetSymbolAddress((void**)&zha, g_zh_a);
    __half* zhb; cudaGetSymbolAddress((void**)&zhb, g_zh_b);
    float* z32a; cudaGetSymbolAddress((void**)&z32a, g_z32_a);
    float* z32b; cudaGetSymbolAddress((void**)&z32b, g_z32_b);

    // zero + W transpose + counter reset, then init+prep fused
    zero_wt_kernel<<<(n + 255) / 256, 256>>>(W, n);
    init_gemm<<<(n + 31) / 32, 96>>>(X, b, n);

    // CSR by dst (deterministic: rows sorted by src); perm fused into scans
    hist_kernel<<<(m + 255) / 256, 256>>>(edges, m);
    int sblocks = (n + 1023) / 1024;   // 49 <= 64
    scan1_kernel<<<sblocks, 1024>>>(n);
    scan2_kernel<<<1, 64>>>(sblocks, n);
    scan3_kernel<<<(n + 255) / 256, 256>>>(n);
    scatter_kernel<<<(m + 255) / 256, 256>>>(edges, m);
    sort_rows<<<(n + 255) / 256, 256>>>(n);

    // single persistent kernel: all 4 routing layers with device barriers
    routing_all<<<ROUTE_GRID, 128, ROUTE_SMEM>>>(zha, z32a, zhb, z32b,
                                                 (float*)d_out, n);
}